// round 7
// baseline (speedup 1.0000x reference)
#include <cuda_runtime.h>
#include <math.h>

// ---------------------------------------------------------------------------
// Problem constants
// ---------------------------------------------------------------------------
#define BB     128
#define TSTEPS 31
#define NCLS   111
#define NPOS   256          // H*W = 8*32
#define CONV_TILES 288      // 4608/16

// ---------------------------------------------------------------------------
// Scratch: one __device__ global array (no runtime allocation allowed)
// ---------------------------------------------------------------------------
#define OF_FPROJ  0u          // 32768*512       = 16777216
#define OF_EK0    16777216u   // 112*2048        = 229376
#define OF_ST     17006592u   // 8 * 65536       = 524288
#define OF_H1ALL  17530880u   // 31*65536        = 2031616
#define OF_HP     19562496u   // 31*65536        = 2031616
#define OF_ATT    21594112u   // 31*128*256      = 1015808
#define OF_GLIM   22609920u   // 31*65536        = 2031616
#define SCRATCH_TOTAL 24641536u
__device__ float g_scratch[SCRATCH_TOTAL];

// ---------------------------------------------------------------------------
// Helpers
// ---------------------------------------------------------------------------
__device__ __forceinline__ float tf32r(float x) {
    unsigned u; asm("cvt.rna.tf32.f32 %0, %1;" : "=r"(u) : "f"(x));
    return __uint_as_float(u);
}
__device__ __forceinline__ float fast_tanh(float x) {
    float r; asm("tanh.approx.f32 %0, %1;" : "=f"(r) : "f"(x));
    return r;
}
__device__ __forceinline__ void mma_tf32(float* d, const unsigned* a, const unsigned* b) {
    asm volatile(
        "mma.sync.aligned.m16n8k8.row.col.f32.tf32.tf32.f32 "
        "{%0,%1,%2,%3}, {%4,%5,%6,%7}, {%8,%9}, {%0,%1,%2,%3};\n"
        : "+f"(d[0]), "+f"(d[1]), "+f"(d[2]), "+f"(d[3])
        : "r"(a[0]), "r"(a[1]), "r"(a[2]), "r"(a[3]), "r"(b[0]), "r"(b[1]));
}

// ---------------------------------------------------------------------------
// Ek0[s][n] = sum_k embed_W[s][k] * k0[k][n] ; row 111 = zeros (SOS)
// grid (8, 112), 256 threads
// ---------------------------------------------------------------------------
__global__ __launch_bounds__(256) void ek0_kernel(
    const float* __restrict__ eW, const float* __restrict__ k0,
    float* __restrict__ Ek0)
{
    const int n = blockIdx.x * 256 + threadIdx.x;
    const int s = blockIdx.y;
    float a0 = 0.f, a1 = 0.f, a2 = 0.f, a3 = 0.f;
    if (s < 111) {
        const float* e = eW + s * 512;
        for (int k = 0; k < 512; k += 4) {
            a0 += e[k + 0] * k0[(size_t)(k + 0) * 2048 + n];
            a1 += e[k + 1] * k0[(size_t)(k + 1) * 2048 + n];
            a2 += e[k + 2] * k0[(size_t)(k + 2) * 2048 + n];
            a3 += e[k + 3] * k0[(size_t)(k + 3) * 2048 + n];
        }
    }
    Ek0[(size_t)s * 2048 + n] = (a0 + a1) + (a2 + a3);
}

// ---------------------------------------------------------------------------
// Conv 3x3 SAME as implicit GEMM, tf32 mma.sync. M=32768, N=512, K=4608.
// Block 128x128, KT=16. 256 threads = 8 warps (2m x 4n), warp tile 64x32.
// grid (4, 256)
// ---------------------------------------------------------------------------
__global__ __launch_bounds__(256) void conv_kernel(
    const float* __restrict__ F, const float* __restrict__ Wf,
    const float* __restrict__ bf, float* __restrict__ fproj)
{
    __shared__ float As[16][136];   // [k][m], stride 136 -> conflict-free frags
    __shared__ float Bs[16][136];   // [k][n]

    const int tid = threadIdx.x;
    const int lane = tid & 31, warp = tid >> 5;
    const int wm = warp >> 2, wn = warp & 3;
    const int gid = lane >> 2, tig = lane & 3;
    const int mBase = blockIdx.y * 128, nBase = blockIdx.x * 128;

    // A loader: this thread's fixed pixel
    const int am = tid >> 1;
    const int ak = (tid & 1) * 8;
    const int gm = mBase + am;
    const int ab = gm >> 8;
    const int ah = (gm >> 5) & 7;
    const int aw = gm & 31;
    // B loader
    const int bk = tid >> 4;
    const int bn = (tid & 15) * 8;

    float acc[4][4][4];
#pragma unroll
    for (int i = 0; i < 4; i++)
#pragma unroll
        for (int j = 0; j < 4; j++)
#pragma unroll
            for (int c = 0; c < 4; c++) acc[i][j][c] = 0.f;

    for (int kt = 0; kt < CONV_TILES; kt++) {
        const int kbase = kt << 4;
        const int r = kt >> 5;             // (kh*3+kw), k-tile never crosses ci=512
        const int ci0 = (kt & 31) << 4;
        const int kh = r / 3;
        const int kw = r - kh * 3;
        const int ih = ah + kh - 1, iw = aw + kw - 1;

        float4 av0 = make_float4(0.f, 0.f, 0.f, 0.f), av1 = av0;
        if ((unsigned)ih < 8u && (unsigned)iw < 32u) {
            const float* p = F + ((size_t)((ab * 8 + ih) * 32 + iw) << 9) + ci0 + ak;
            av0 = *(const float4*)p;
            av1 = *(const float4*)(p + 4);
        }
        const float* q = Wf + (size_t)(kbase + bk) * 512 + nBase + bn;
        float4 bv0 = *(const float4*)q;
        float4 bv1 = *(const float4*)(q + 4);

        __syncthreads();
        As[ak + 0][am] = tf32r(av0.x); As[ak + 1][am] = tf32r(av0.y);
        As[ak + 2][am] = tf32r(av0.z); As[ak + 3][am] = tf32r(av0.w);
        As[ak + 4][am] = tf32r(av1.x); As[ak + 5][am] = tf32r(av1.y);
        As[ak + 6][am] = tf32r(av1.z); As[ak + 7][am] = tf32r(av1.w);
        Bs[bk][bn + 0] = tf32r(bv0.x); Bs[bk][bn + 1] = tf32r(bv0.y);
        Bs[bk][bn + 2] = tf32r(bv0.z); Bs[bk][bn + 3] = tf32r(bv0.w);
        Bs[bk][bn + 4] = tf32r(bv1.x); Bs[bk][bn + 5] = tf32r(bv1.y);
        Bs[bk][bn + 6] = tf32r(bv1.z); Bs[bk][bn + 7] = tf32r(bv1.w);
        __syncthreads();

#pragma unroll
        for (int ks = 0; ks < 16; ks += 8) {
            unsigned afr[4][4], bfr[4][2];
#pragma unroll
            for (int mf = 0; mf < 4; mf++) {
                const int m0 = wm * 64 + mf * 16 + gid;
                afr[mf][0] = __float_as_uint(As[ks + tig][m0]);
                afr[mf][1] = __float_as_uint(As[ks + tig][m0 + 8]);
                afr[mf][2] = __float_as_uint(As[ks + tig + 4][m0]);
                afr[mf][3] = __float_as_uint(As[ks + tig + 4][m0 + 8]);
            }
#pragma unroll
            for (int nf = 0; nf < 4; nf++) {
                const int n0 = wn * 32 + nf * 8 + gid;
                bfr[nf][0] = __float_as_uint(Bs[ks + tig][n0]);
                bfr[nf][1] = __float_as_uint(Bs[ks + tig + 4][n0]);
            }
#pragma unroll
            for (int mf = 0; mf < 4; mf++)
#pragma unroll
                for (int nf = 0; nf < 4; nf++)
                    mma_tf32(acc[mf][nf], afr[mf], bfr[nf]);
        }
    }

#pragma unroll
    for (int mf = 0; mf < 4; mf++) {
        const int row = mBase + wm * 64 + mf * 16 + gid;
#pragma unroll
        for (int nf = 0; nf < 4; nf++) {
            const int col = nBase + wn * 32 + nf * 8 + tig * 2;
            const float bb0 = bf[col], bb1 = bf[col + 1];
            fproj[(size_t)row * 512 + col]           = acc[mf][nf][0] + bb0;
            fproj[(size_t)row * 512 + col + 1]       = acc[mf][nf][1] + bb1;
            fproj[(size_t)(row + 8) * 512 + col]     = acc[mf][nf][2] + bb0;
            fproj[(size_t)(row + 8) * 512 + col + 1] = acc[mf][nf][3] + bb1;
        }
    }
}

// ---------------------------------------------------------------------------
// Fused LSTM cell: z = [Ek0 gather] + x1@W1 + [x2@W2] + bias ; gates i,f,g,o
// grid (16 jj-tiles, 8 m-tiles of 16 rows), 256 threads (32 jj x 8 m)
// ---------------------------------------------------------------------------
__global__ __launch_bounds__(256) void lstm_cell(
    const float* __restrict__ Ek0, const int* __restrict__ gt, int tstep,
    const float* __restrict__ x1, const float* __restrict__ W1,
    const float* __restrict__ x2, const float* __restrict__ W2,
    const float* __restrict__ bias, const float* __restrict__ c_in,
    float* __restrict__ h_out, float* __restrict__ c_out,
    float* __restrict__ h_out2)
{
    __shared__ float Xs[16][17];
    __shared__ float Ws[16][132];

    const int tid = threadIdx.x;
    const int jjl = tid & 31, mthr = tid >> 5;
    const int jjBase = blockIdx.x * 32;
    const int mBase = blockIdx.y * 16;
    const int jjg = jjBase + jjl;

    const int xm = tid >> 4, xk = tid & 15;
    const int wk = tid >> 4, wc = (tid & 15) * 8;
    const int wcol = (wc >> 5) * 512 + jjBase + (wc & 31);

    int row[2];
    row[0] = mBase + mthr;
    row[1] = row[0] + 8;

    float acc[2][4];
#pragma unroll
    for (int r = 0; r < 2; r++)
#pragma unroll
        for (int g = 0; g < 4; g++) acc[r][g] = bias[g * 512 + jjg];

    if (Ek0) {
#pragma unroll
        for (int r = 0; r < 2; r++) {
            const int sym = (tstep == 0) ? 111 : gt[row[r] * TSTEPS + tstep - 1];
            const float* e = Ek0 + (size_t)sym * 2048;
#pragma unroll
            for (int g = 0; g < 4; g++) acc[r][g] += e[g * 512 + jjg];
        }
    }

    for (int pass = 0; pass < 2; pass++) {
        const float* X = pass ? x2 : x1;
        const float* W = pass ? W2 : W1;
        if (!X) continue;                 // uniform across block: safe with barriers
        for (int kt = 0; kt < 512; kt += 16) {
            const float xv = X[(size_t)(mBase + xm) * 512 + kt + xk];
            const float* wp = W + (size_t)(kt + wk) * 2048 + wcol;
            const float4 w0 = *(const float4*)wp;
            const float4 w1 = *(const float4*)(wp + 4);
            __syncthreads();
            Xs[xk][xm] = xv;
            *(float4*)&Ws[wk][wc] = w0;
            *(float4*)&Ws[wk][wc + 4] = w1;
            __syncthreads();
#pragma unroll
            for (int k = 0; k < 16; k++) {
                const float a0 = Xs[k][mthr], a1 = Xs[k][mthr + 8];
                const float b0 = Ws[k][jjl],       b1 = Ws[k][32 + jjl];
                const float b2 = Ws[k][64 + jjl],  b3 = Ws[k][96 + jjl];
                acc[0][0] += a0 * b0; acc[0][1] += a0 * b1;
                acc[0][2] += a0 * b2; acc[0][3] += a0 * b3;
                acc[1][0] += a1 * b0; acc[1][1] += a1 * b1;
                acc[1][2] += a1 * b2; acc[1][3] += a1 * b3;
            }
        }
    }

#pragma unroll
    for (int r = 0; r < 2; r++) {
        const float iv = acc[r][0], fv = acc[r][1], gv = acc[r][2], ov = acc[r][3];
        const float ci = c_in ? c_in[(size_t)row[r] * 512 + jjg] : 0.f;
        const float si = 1.f / (1.f + expf(-iv));
        const float sf = 1.f / (1.f + expf(-fv));
        const float so = 1.f / (1.f + expf(-ov));
        const float c2 = sf * ci + si * tanhf(gv);
        const float h2 = so * tanhf(c2);
        h_out[(size_t)row[r] * 512 + jjg] = h2;
        c_out[(size_t)row[r] * 512 + jjg] = c2;
        if (h_out2) h_out2[(size_t)row[r] * 512 + jjg] = h2;
    }
}

// ---------------------------------------------------------------------------
// Generic fp32 GEMM: C = [A1|A2] @ W (+bias).  BM=64, BN=64, BK=16.
// mode 0: C[row*N+col] ; mode 1: logits remap out[(b*31+t)*111+col]
// ---------------------------------------------------------------------------
__global__ __launch_bounds__(256) void gemm_fused(
    const float* __restrict__ A1, const float* __restrict__ A2,
    const float* __restrict__ W, const float* __restrict__ bias,
    float* __restrict__ C, int N, int K, int mode)
{
    __shared__ float sA[16][65];
    __shared__ float sB[16][68];
    const int tid = threadIdx.x;
    const int tx = tid & 15, ty = tid >> 4;
    const int mBase = blockIdx.y * 64, nBase = blockIdx.x * 64;

    const int lam = tid >> 2, lak = (tid & 3) * 4;
    const int lbk = tid >> 4, lbn = (tid & 15) * 4;

    float acc[4][4];
#pragma unroll
    for (int i = 0; i < 4; i++)
#pragma unroll
        for (int j = 0; j < 4; j++) acc[i][j] = 0.f;

    for (int k0 = 0; k0 < K; k0 += 16) {
        float av[4], bv[4];
#pragma unroll
        for (int i = 0; i < 4; i++) {
            const int kk = k0 + lak + i;
            av[i] = (kk < 512) ? A1[(size_t)(mBase + lam) * 512 + kk]
                               : A2[(size_t)(mBase + lam) * 512 + kk - 512];
        }
#pragma unroll
        for (int i = 0; i < 4; i++) {
            const int nn = nBase + lbn + i;
            bv[i] = (nn < N) ? W[(size_t)(k0 + lbk) * N + nn] : 0.f;
        }
        __syncthreads();
#pragma unroll
        for (int i = 0; i < 4; i++) sA[lak + i][lam] = av[i];
#pragma unroll
        for (int i = 0; i < 4; i++) sB[lbk][lbn + i] = bv[i];
        __syncthreads();
#pragma unroll
        for (int kk = 0; kk < 16; kk++) {
            float a[4], b[4];
#pragma unroll
            for (int i = 0; i < 4; i++) a[i] = sA[kk][ty * 4 + i];
#pragma unroll
            for (int j = 0; j < 4; j++) b[j] = sB[kk][tx * 4 + j];
#pragma unroll
            for (int i = 0; i < 4; i++)
#pragma unroll
                for (int j = 0; j < 4; j++) acc[i][j] += a[i] * b[j];
        }
    }

#pragma unroll
    for (int i = 0; i < 4; i++) {
        const int row = mBase + ty * 4 + i;
#pragma unroll
        for (int j = 0; j < 4; j++) {
            const int col = nBase + tx * 4 + j;
            if (col < N) {
                float v = acc[i][j] + (bias ? bias[col] : 0.f);
                if (mode == 0) {
                    C[(size_t)row * N + col] = v;
                } else {
                    const int t = row >> 7, b = row & 127;
                    C[(size_t)(b * TSTEPS + t) * NCLS + col] = v;
                }
            }
        }
    }
}

// ---------------------------------------------------------------------------
// Attention logits: att[t,b,pos] = sum_ch tanh(fproj[b,pos,ch]+hp[t,b,ch])*wa[ch]
// fproj register-resident (read once). grid (8 pos-chunks, 128 b), 256 thr
// ---------------------------------------------------------------------------
__global__ __launch_bounds__(256) void att_kernel(
    const float* __restrict__ fproj, const float* __restrict__ hp,
    const float* __restrict__ wa, float* __restrict__ att)
{
    __shared__ float sHp[8 * 65];
    __shared__ float sWa[8 * 65];
    const int tid = threadIdx.x;
    const int posl = tid >> 3, tch = tid & 7;
    const int b = blockIdx.y, pos0 = blockIdx.x * 32;
    const int ch0 = tch * 64;

    float fr[64];
    const float* fp = fproj + (size_t)(b * NPOS + pos0 + posl) * 512 + ch0;
#pragma unroll
    for (int i = 0; i < 16; i++) {
        const float4 v = *(const float4*)(fp + i * 4);
        fr[i * 4 + 0] = v.x; fr[i * 4 + 1] = v.y;
        fr[i * 4 + 2] = v.z; fr[i * 4 + 3] = v.w;
    }
    for (int k = tid; k < 512; k += 256)
        sWa[(k >> 6) * 65 + (k & 63)] = wa[k];

    for (int t = 0; t < TSTEPS; t++) {
        __syncthreads();
        const float* hrow = hp + (size_t)(t * BB + b) * 512;
        for (int k = tid; k < 512; k += 256)
            sHp[(k >> 6) * 65 + (k & 63)] = hrow[k];
        __syncthreads();
        float s = 0.f;
#pragma unroll
        for (int i = 0; i < 64; i++) {
            const float x = fr[i] + sHp[tch * 65 + i];
            s += fast_tanh(x) * sWa[tch * 65 + i];
        }
        s += __shfl_down_sync(0xffffffffu, s, 4, 8);
        s += __shfl_down_sync(0xffffffffu, s, 2, 8);
        s += __shfl_down_sync(0xffffffffu, s, 1, 8);
        if (tch == 0)
            att[(size_t)(t * BB + b) * NPOS + pos0 + posl] = s;
    }
}

// ---------------------------------------------------------------------------
// Softmax over 256 positions per (t,b). grid 3968, 256 threads
// ---------------------------------------------------------------------------
__global__ __launch_bounds__(256) void softmax_kernel(float* __restrict__ att)
{
    const int row = blockIdx.x, tid = threadIdx.x;
    const int lane = tid & 31, warp = tid >> 5;
    __shared__ float rmax[8], rsum[8];
    const float v = att[(size_t)row * NPOS + tid];
    float m = v;
#pragma unroll
    for (int o = 16; o; o >>= 1) m = fmaxf(m, __shfl_xor_sync(0xffffffffu, m, o));
    if (lane == 0) rmax[warp] = m;
    __syncthreads();
    float M = rmax[0];
#pragma unroll
    for (int i = 1; i < 8; i++) M = fmaxf(M, rmax[i]);
    const float e = __expf(v - M);
    float s = e;
#pragma unroll
    for (int o = 16; o; o >>= 1) s += __shfl_xor_sync(0xffffffffu, s, o);
    if (lane == 0) rsum[warp] = s;
    __syncthreads();
    float S = 0.f;
#pragma unroll
    for (int i = 0; i < 8; i++) S += rsum[i];
    att[(size_t)row * NPOS + tid] = e / S;
}

// ---------------------------------------------------------------------------
// Glimpse: glim[t,b,c] = sum_pos att[t,b,pos] * features[b,pos,c]
// features tile read once per block. grid (16 ch-chunks, 128 b), 256 thr
// ---------------------------------------------------------------------------
__global__ __launch_bounds__(256) void glimpse_kernel(
    const float* __restrict__ F, const float* __restrict__ att,
    float* __restrict__ glim)
{
    __shared__ float sF[NPOS * 32];
    __shared__ float sA[NPOS];
    __shared__ float sP[8][33];
    const int tid = threadIdx.x;
    const int b = blockIdx.y, ch0 = blockIdx.x * 32;

    for (int idx = tid; idx < NPOS * 32; idx += 256) {
        const int pos = idx >> 5, ch = idx & 31;
        sF[pos * 32 + ch] = F[(size_t)(b * NPOS + pos) * 512 + ch0 + ch];
    }
    const int pg = tid >> 5, ch = tid & 31;

    for (int t = 0; t < TSTEPS; t++) {
        __syncthreads();
        sA[tid] = att[(size_t)(t * BB + b) * NPOS + tid];
        __syncthreads();
        float s = 0.f;
#pragma unroll
        for (int p = 0; p < 32; p++)
            s += sA[pg * 32 + p] * sF[(pg * 32 + p) * 32 + ch];
        sP[pg][ch] = s;
        __syncthreads();
        if (tid < 32) {
            float g = 0.f;
#pragma unroll
            for (int i = 0; i < 8; i++) g += sP[i][tid];
            glim[(size_t)(t * BB + b) * 512 + ch0 + tid] = g;
        }
    }
}

// ---------------------------------------------------------------------------
// Launch
// ---------------------------------------------------------------------------
extern "C" void kernel_launch(void* const* d_in, const int* in_sizes, int n_in,
                              void* d_out, int out_size)
{
    const float* features = (const float*)d_in[0];
    const float* holistic = (const float*)d_in[1];
    const int*   gt       = (const int*)  d_in[2];
    const float* embed_W  = (const float*)d_in[3];
    const float* k0   = (const float*)d_in[4];
    const float* rk0  = (const float*)d_in[5];
    const float* b0   = (const float*)d_in[6];
    const float* k1   = (const float*)d_in[7];
    const float* rk1  = (const float*)d_in[8];
    const float* b1   = (const float*)d_in[9];
    const float* Wh   = (const float*)d_in[10];
    const float* Wf   = (const float*)d_in[11];
    const float* bf   = (const float*)d_in[12];
    const float* wa   = (const float*)d_in[13];
    const float* outW = (const float*)d_in[14];
    const float* outb = (const float*)d_in[15];
    float* out = (float*)d_out;

    float* S = nullptr;
    cudaGetSymbolAddress((void**)&S, g_scratch);

    float* fproj = S + OF_FPROJ;
    float* Ek0   = S + OF_EK0;
    float* h0b[2] = { S + OF_ST,          S + OF_ST + 65536 };
    float* c0b[2] = { S + OF_ST + 131072, S + OF_ST + 196608 };
    float* h1b[2] = { S + OF_ST + 262144, S + OF_ST + 327680 };
    float* c1b[2] = { S + OF_ST + 393216, S + OF_ST + 458752 };
    float* h1all = S + OF_H1ALL;
    float* hp    = S + OF_HP;
    float* att   = S + OF_ATT;
    float* glim  = S + OF_GLIM;

    // Big conv first (longest), then embedding table
    conv_kernel<<<dim3(4, 256), 256>>>(features, Wf, bf, fproj);
    ek0_kernel<<<dim3(8, 112), 256>>>(embed_W, k0, Ek0);

    // Prime the stacked LSTM with the holistic vector (zero state)
    lstm_cell<<<dim3(16, 8), 256>>>(nullptr, nullptr, 0,
        holistic, k0, nullptr, nullptr, b0, nullptr, h0b[0], c0b[0], nullptr);
    lstm_cell<<<dim3(16, 8), 256>>>(nullptr, nullptr, 0,
        h0b[0], k1, nullptr, nullptr, b1, nullptr, h1b[0], c1b[0], nullptr);

    // Sequential chain (teacher forcing -> x@k0 is a gather of Ek0)
    for (int t = 0; t < TSTEPS; t++) {
        const int p = t & 1, q = p ^ 1;
        lstm_cell<<<dim3(16, 8), 256>>>(Ek0, gt, t,
            h0b[p], rk0, nullptr, nullptr, b0, c0b[p], h0b[q], c0b[q], nullptr);
        lstm_cell<<<dim3(16, 8), 256>>>(nullptr, nullptr, 0,
            h0b[q], k1, h1b[p], rk1, b1, c1b[p], h1b[q], c1b[q],
            h1all + (size_t)t * BB * 512);
    }

    // Batched epilogue over all 31 steps
    gemm_fused<<<dim3(8, 62), 256>>>(h1all, nullptr, Wh, nullptr, hp, 512, 512, 0);
    att_kernel<<<dim3(8, 128), 256>>>(fproj, hp, wa, att);
    softmax_kernel<<<TSTEPS * BB, 256>>>(att);
    glimpse_kernel<<<dim3(16, 128), 256>>>(features, att, glim);
    gemm_fused<<<dim3(2, 62), 256>>>(h1all, glim, outW, outb, out, NCLS, 1024, 1);
}

// round 8
// speedup vs baseline: 1.3773x; 1.3773x over previous
#include <cuda_runtime.h>
#include <math.h>

// ---------------------------------------------------------------------------
// Problem constants
// ---------------------------------------------------------------------------
#define BB     128
#define TSTEPS 31
#define NCLS   111
#define NPOS   256          // H*W = 8*32
#define CONV_TILES 288      // 4608/16

// ---------------------------------------------------------------------------
// Scratch: one __device__ global array (no runtime allocation allowed)
// ---------------------------------------------------------------------------
#define OF_FPROJ  0u          // 32768*512       = 16777216
#define OF_EK0    16777216u   // 112*2048        = 229376
#define OF_ST     17006592u   // 8 * 65536       = 524288
#define OF_H1ALL  17530880u   // 31*65536        = 2031616
#define OF_HP     19562496u   // 31*65536        = 2031616
#define OF_ATT    21594112u   // 31*128*256      = 1015808
#define OF_GLIM   22609920u   // 31*65536        = 2031616
#define OF_WT     24641536u   // 4 * 512*2048    = 4194304
#define SCRATCH_TOTAL 28835840u
__device__ float g_scratch[SCRATCH_TOTAL];

// ---------------------------------------------------------------------------
// Helpers
// ---------------------------------------------------------------------------
__device__ __forceinline__ float tf32r(float x) {
    unsigned u; asm("cvt.rna.tf32.f32 %0, %1;" : "=r"(u) : "f"(x));
    return __uint_as_float(u);
}
__device__ __forceinline__ float fast_tanh(float x) {
    float r; asm("tanh.approx.f32 %0, %1;" : "=f"(r) : "f"(x));
    return r;
}
__device__ __forceinline__ void mma_tf32(float* d, const unsigned* a, const unsigned* b) {
    asm volatile(
        "mma.sync.aligned.m16n8k8.row.col.f32.tf32.tf32.f32 "
        "{%0,%1,%2,%3}, {%4,%5,%6,%7}, {%8,%9}, {%0,%1,%2,%3};\n"
        : "+f"(d[0]), "+f"(d[1]), "+f"(d[2]), "+f"(d[3])
        : "r"(a[0]), "r"(a[1]), "r"(a[2]), "r"(a[3]), "r"(b[0]), "r"(b[1]));
}
__device__ __forceinline__ void cp16(float* dst, const float* src, bool v) {
    unsigned d = (unsigned)__cvta_generic_to_shared(dst);
    int sz = v ? 16 : 0;
    asm volatile("cp.async.ca.shared.global [%0], [%1], 16, %2;\n"
                 :: "r"(d), "l"(src), "r"(sz));
}
#define CP_COMMIT() asm volatile("cp.async.commit_group;\n" ::: "memory")
#define CP_WAIT(n)  asm volatile("cp.async.wait_group %0;\n" :: "n"(n) : "memory")

// ---------------------------------------------------------------------------
// Ek0[s][n] = sum_k embed_W[s][k] * k0[k][n] ; row 111 = zeros (SOS). fp32.
// ---------------------------------------------------------------------------
__global__ __launch_bounds__(256) void ek0_kernel(
    const float* __restrict__ eW, const float* __restrict__ k0,
    float* __restrict__ Ek0)
{
    const int n = blockIdx.x * 256 + threadIdx.x;
    const int s = blockIdx.y;
    float a0 = 0.f, a1 = 0.f, a2 = 0.f, a3 = 0.f;
    if (s < 111) {
        const float* e = eW + s * 512;
        for (int k = 0; k < 512; k += 4) {
            a0 += e[k + 0] * k0[(size_t)(k + 0) * 2048 + n];
            a1 += e[k + 1] * k0[(size_t)(k + 1) * 2048 + n];
            a2 += e[k + 2] * k0[(size_t)(k + 2) * 2048 + n];
            a3 += e[k + 3] * k0[(size_t)(k + 3) * 2048 + n];
        }
    }
    Ek0[(size_t)s * 2048 + n] = (a0 + a1) + (a2 + a3);
}

// ---------------------------------------------------------------------------
// Reorder LSTM weights into gate-interleaved layout with tf32 rounding:
//   out[k][j*4+g] = tf32(in[k][g*512+j])
// ---------------------------------------------------------------------------
__global__ __launch_bounds__(256) void reorder_w(
    const float* __restrict__ in, float* __restrict__ out)
{
    const int k = blockIdx.x;
    for (int n = threadIdx.x; n < 2048; n += 256) {
        const int g = n & 3, j = n >> 2;
        out[(size_t)k * 2048 + n] = tf32r(in[(size_t)k * 2048 + g * 512 + j]);
    }
}

// ---------------------------------------------------------------------------
// Conv 3x3 SAME as implicit GEMM, tf32 mma, 2-stage cp.async pipeline.
// M=32768, N=512, K=4608. Block 128x128, BK=16, 256 thr (8 warps 2m x 4n).
// grid (4, 256)
// ---------------------------------------------------------------------------
__global__ __launch_bounds__(256) void conv_kernel(
    const float* __restrict__ F, const float* __restrict__ Wf,
    const float* __restrict__ bf, float* __restrict__ fproj)
{
    __shared__ float As[2][128][20];   // [stage][m][k], pitch 20 -> conflict-free
    __shared__ float Bs[2][16][132];   // [stage][k][n]

    const int tid = threadIdx.x;
    const int lane = tid & 31, warp = tid >> 5;
    const int wm = warp >> 2, wn = warp & 3;
    const int gid = lane >> 2, tig = lane & 3;
    const int mBase = blockIdx.y * 128, nBase = blockIdx.x * 128;

    // A loader: fixed pixel per thread, 8 channels (2x16B)
    const int am = tid >> 1;
    const int ak = (tid & 1) * 8;
    const int gm = mBase + am;
    const int ab = gm >> 8;
    const int ah = (gm >> 5) & 7;
    const int aw = gm & 31;
    // B loader: 8 out-channels (2x16B)
    const int bk = tid >> 4;
    const int bn = (tid & 15) * 8;

    auto issue = [&](int kt, int s) {
        const int r = kt >> 5;               // kh*3+kw (k-tile never crosses ci)
        const int ci0 = (kt & 31) << 4;
        const int kh = r / 3;
        const int kw = r - kh * 3;
        const int ih = ah + kh - 1, iw = aw + kw - 1;
        const bool v = ((unsigned)ih < 8u) && ((unsigned)iw < 32u);
        const float* p = v ? (F + (((size_t)(ab * 8 + ih) * 32 + iw) << 9) + ci0 + ak) : F;
        cp16(&As[s][am][ak],     p,     v);
        cp16(&As[s][am][ak + 4], p + 4, v);
        const float* q = Wf + ((size_t)(kt * 16 + bk)) * 512 + nBase + bn;
        cp16(&Bs[s][bk][bn],     q,     true);
        cp16(&Bs[s][bk][bn + 4], q + 4, true);
    };

    float acc[4][4][4];
#pragma unroll
    for (int i = 0; i < 4; i++)
#pragma unroll
        for (int j = 0; j < 4; j++)
#pragma unroll
            for (int c = 0; c < 4; c++) acc[i][j][c] = 0.f;

    issue(0, 0); CP_COMMIT();
    issue(1, 1); CP_COMMIT();

    for (int kt = 0; kt < CONV_TILES; kt++) {
        const int s = kt & 1;
        if (kt + 1 < CONV_TILES) { CP_WAIT(1); } else { CP_WAIT(0); }
        __syncthreads();

#pragma unroll
        for (int ks = 0; ks < 16; ks += 8) {
            unsigned afr[4][4], bfr[4][2];
#pragma unroll
            for (int mf = 0; mf < 4; mf++) {
                const int m0 = wm * 64 + mf * 16 + gid;
                afr[mf][0] = __float_as_uint(As[s][m0][ks + tig]);
                afr[mf][1] = __float_as_uint(As[s][m0 + 8][ks + tig]);
                afr[mf][2] = __float_as_uint(As[s][m0][ks + tig + 4]);
                afr[mf][3] = __float_as_uint(As[s][m0 + 8][ks + tig + 4]);
            }
#pragma unroll
            for (int nf = 0; nf < 4; nf++) {
                const int n0 = wn * 32 + nf * 8 + gid;
                bfr[nf][0] = __float_as_uint(Bs[s][ks + tig][n0]);
                bfr[nf][1] = __float_as_uint(Bs[s][ks + tig + 4][n0]);
            }
#pragma unroll
            for (int mf = 0; mf < 4; mf++)
#pragma unroll
                for (int nf = 0; nf < 4; nf++)
                    mma_tf32(acc[mf][nf], afr[mf], bfr[nf]);
        }
        __syncthreads();
        if (kt + 2 < CONV_TILES) { issue(kt + 2, s); CP_COMMIT(); }
    }

#pragma unroll
    for (int mf = 0; mf < 4; mf++) {
        const int row = mBase + wm * 64 + mf * 16 + gid;
#pragma unroll
        for (int nf = 0; nf < 4; nf++) {
            const int col = nBase + wn * 32 + nf * 8 + tig * 2;
            const float bb0 = bf[col], bb1 = bf[col + 1];
            fproj[(size_t)row * 512 + col]           = acc[mf][nf][0] + bb0;
            fproj[(size_t)row * 512 + col + 1]       = acc[mf][nf][1] + bb1;
            fproj[(size_t)(row + 8) * 512 + col]     = acc[mf][nf][2] + bb0;
            fproj[(size_t)(row + 8) * 512 + col + 1] = acc[mf][nf][3] + bb1;
        }
    }
}

// ---------------------------------------------------------------------------
// Tensor-core LSTM cell. Z[128,2048'] = X1@W1t (+X2@W2t); W't interleaved
// n' = j*4+gate so one block owns all 4 gates of its j's. Fused gating.
// Block 64m x 32n', BK=16, 128 threads (4 warps 2x2, warp tile 32x16).
// grid (64, 2)
// ---------------------------------------------------------------------------
__global__ __launch_bounds__(128) void lstm_tc(
    const float* __restrict__ Ek0, const int* __restrict__ gt, int tstep,
    const float* __restrict__ X1, const float* __restrict__ W1t,
    const float* __restrict__ X2, const float* __restrict__ W2t,
    const float* __restrict__ bias, const float* __restrict__ c_in,
    float* __restrict__ h_out, float* __restrict__ c_out,
    float* __restrict__ h_out2)
{
    __shared__ float As[16][68];   // [k][m]
    __shared__ float Bs[16][40];   // [k][n'] pitch 40 floats = 160B (16B aligned)
    __shared__ float Zs[64][33];

    const int tid = threadIdx.x;
    const int lane = tid & 31, warp = tid >> 5;
    const int wm = warp >> 1, wn = warp & 1;
    const int gid = lane >> 2, tig = lane & 3;
    const int nBase = blockIdx.x * 32;
    const int mBase = blockIdx.y * 64;

    const int am = tid >> 1, ak = (tid & 1) * 8;   // A: 64 x 16
    const int bk = tid >> 3, bn = (tid & 7) * 4;   // B: 16 x 32

    const int Ktot = X2 ? 1024 : 512;

    float acc[2][2][4];
#pragma unroll
    for (int i = 0; i < 2; i++)
#pragma unroll
        for (int j = 0; j < 2; j++)
#pragma unroll
            for (int c = 0; c < 4; c++) acc[i][j][c] = 0.f;

    // register prefetch of global tiles
    float4 aR0, aR1, bR;
    {
        const float* ap = X1 + (size_t)(mBase + am) * 512 + ak;
        aR0 = *(const float4*)ap;
        aR1 = *(const float4*)(ap + 4);
        bR  = *(const float4*)(W1t + (size_t)bk * 2048 + nBase + bn);
    }

    for (int kt = 0; kt < Ktot; kt += 16) {
        __syncthreads();
        As[ak + 0][am] = tf32r(aR0.x); As[ak + 1][am] = tf32r(aR0.y);
        As[ak + 2][am] = tf32r(aR0.z); As[ak + 3][am] = tf32r(aR0.w);
        As[ak + 4][am] = tf32r(aR1.x); As[ak + 5][am] = tf32r(aR1.y);
        As[ak + 6][am] = tf32r(aR1.z); As[ak + 7][am] = tf32r(aR1.w);
        *(float4*)&Bs[bk][bn] = bR;    // weights pre-rounded to tf32
        __syncthreads();

        const int kn = kt + 16;
        if (kn < Ktot) {
            const float* X = (kn < 512) ? X1 : X2;
            const float* W = (kn < 512) ? W1t : W2t;
            const int kk = kn & 511;
            const float* ap = X + (size_t)(mBase + am) * 512 + kk + ak;
            aR0 = *(const float4*)ap;
            aR1 = *(const float4*)(ap + 4);
            bR  = *(const float4*)(W + (size_t)(kk + bk) * 2048 + nBase + bn);
        }

#pragma unroll
        for (int ks = 0; ks < 16; ks += 8) {
            unsigned af[2][4], bf2[2][2];
#pragma unroll
            for (int mf = 0; mf < 2; mf++) {
                const int m0 = wm * 32 + mf * 16 + gid;
                af[mf][0] = __float_as_uint(As[ks + tig][m0]);
                af[mf][1] = __float_as_uint(As[ks + tig][m0 + 8]);
                af[mf][2] = __float_as_uint(As[ks + tig + 4][m0]);
                af[mf][3] = __float_as_uint(As[ks + tig + 4][m0 + 8]);
            }
#pragma unroll
            for (int nf = 0; nf < 2; nf++) {
                const int n0 = wn * 16 + nf * 8 + gid;
                bf2[nf][0] = __float_as_uint(Bs[ks + tig][n0]);
                bf2[nf][1] = __float_as_uint(Bs[ks + tig + 4][n0]);
            }
#pragma unroll
            for (int mf = 0; mf < 2; mf++)
#pragma unroll
                for (int nf = 0; nf < 2; nf++)
                    mma_tf32(acc[mf][nf], af[mf], bf2[nf]);
        }
    }

    // Z frags -> smem
    __syncthreads();
#pragma unroll
    for (int mf = 0; mf < 2; mf++) {
        const int row = wm * 32 + mf * 16 + gid;
#pragma unroll
        for (int nf = 0; nf < 2; nf++) {
            const int col = wn * 16 + nf * 8 + tig * 2;
            Zs[row][col]         = acc[mf][nf][0];
            Zs[row][col + 1]     = acc[mf][nf][1];
            Zs[row + 8][col]     = acc[mf][nf][2];
            Zs[row + 8][col + 1] = acc[mf][nf][3];
        }
    }
    __syncthreads();

    // Fused gating: 64 rows x 8 j; thread -> (row, 4 j's)
    const int r  = tid >> 1;
    const int j0 = (tid & 1) * 4;
    const int gr = mBase + r;
    int sym = 0;
    if (Ek0) sym = (tstep == 0) ? 111 : gt[gr * TSTEPS + tstep - 1];

#pragma unroll
    for (int jj = 0; jj < 4; jj++) {
        const int j  = j0 + jj;
        const int jg = (nBase >> 2) + j;
        float zi = Zs[r][j * 4 + 0] + bias[jg];
        float zf = Zs[r][j * 4 + 1] + bias[512 + jg];
        float zg = Zs[r][j * 4 + 2] + bias[1024 + jg];
        float zo = Zs[r][j * 4 + 3] + bias[1536 + jg];
        if (Ek0) {
            const float* e = Ek0 + (size_t)sym * 2048;
            zi += e[jg]; zf += e[512 + jg]; zg += e[1024 + jg]; zo += e[1536 + jg];
        }
        const float ci = c_in ? c_in[(size_t)gr * 512 + jg] : 0.f;
        const float si = 1.f / (1.f + expf(-zi));
        const float sf = 1.f / (1.f + expf(-zf));
        const float so = 1.f / (1.f + expf(-zo));
        const float c2 = sf * ci + si * tanhf(zg);
        const float h2 = so * tanhf(c2);
        h_out[(size_t)gr * 512 + jg] = h2;
        c_out[(size_t)gr * 512 + jg] = c2;
        if (h_out2) h_out2[(size_t)gr * 512 + jg] = h2;
    }
}

// ---------------------------------------------------------------------------
// Generic fp32 GEMM: C = [A1|A2] @ W (+bias).  BM=64, BN=64, BK=16.
// mode 0: C[row*N+col] ; mode 1: logits remap out[(b*31+t)*111+col]
// ---------------------------------------------------------------------------
__global__ __launch_bounds__(256) void gemm_fused(
    const float* __restrict__ A1, const float* __restrict__ A2,
    const float* __restrict__ W, const float* __restrict__ bias,
    float* __restrict__ C, int N, int K, int mode)
{
    __shared__ float sA[16][65];
    __shared__ float sB[16][68];
    const int tid = threadIdx.x;
    const int tx = tid & 15, ty = tid >> 4;
    const int mBase = blockIdx.y * 64, nBase = blockIdx.x * 64;

    const int lam = tid >> 2, lak = (tid & 3) * 4;
    const int lbk = tid >> 4, lbn = (tid & 15) * 4;

    float acc[4][4];
#pragma unroll
    for (int i = 0; i < 4; i++)
#pragma unroll
        for (int j = 0; j < 4; j++) acc[i][j] = 0.f;

    for (int k0 = 0; k0 < K; k0 += 16) {
        float av[4], bv[4];
#pragma unroll
        for (int i = 0; i < 4; i++) {
            const int kk = k0 + lak + i;
            av[i] = (kk < 512) ? A1[(size_t)(mBase + lam) * 512 + kk]
                               : A2[(size_t)(mBase + lam) * 512 + kk - 512];
        }
#pragma unroll
        for (int i = 0; i < 4; i++) {
            const int nn = nBase + lbn + i;
            bv[i] = (nn < N) ? W[(size_t)(k0 + lbk) * N + nn] : 0.f;
        }
        __syncthreads();
#pragma unroll
        for (int i = 0; i < 4; i++) sA[lak + i][lam] = av[i];
#pragma unroll
        for (int i = 0; i < 4; i++) sB[lbk][lbn + i] = bv[i];
        __syncthreads();
#pragma unroll
        for (int kk = 0; kk < 16; kk++) {
            float a[4], b[4];
#pragma unroll
            for (int i = 0; i < 4; i++) a[i] = sA[kk][ty * 4 + i];
#pragma unroll
            for (int j = 0; j < 4; j++) b[j] = sB[kk][tx * 4 + j];
#pragma unroll
            for (int i = 0; i < 4; i++)
#pragma unroll
                for (int j = 0; j < 4; j++) acc[i][j] += a[i] * b[j];
        }
    }

#pragma unroll
    for (int i = 0; i < 4; i++) {
        const int row = mBase + ty * 4 + i;
#pragma unroll
        for (int j = 0; j < 4; j++) {
            const int col = nBase + tx * 4 + j;
            if (col < N) {
                float v = acc[i][j] + (bias ? bias[col] : 0.f);
                if (mode == 0) {
                    C[(size_t)row * N + col] = v;
                } else {
                    const int t = row >> 7, b = row & 127;
                    C[(size_t)(b * TSTEPS + t) * NCLS + col] = v;
                }
            }
        }
    }
}

// ---------------------------------------------------------------------------
// Attention logits: att[t,b,pos] = sum_ch tanh(fproj[b,pos,ch]+hp[t,b,ch])*wa[ch]
// fproj register-resident (read once). grid (8 pos-chunks, 128 b), 256 thr
// ---------------------------------------------------------------------------
__global__ __launch_bounds__(256) void att_kernel(
    const float* __restrict__ fproj, const float* __restrict__ hp,
    const float* __restrict__ wa, float* __restrict__ att)
{
    __shared__ float sHp[8 * 65];
    __shared__ float sWa[8 * 65];
    const int tid = threadIdx.x;
    const int posl = tid >> 3, tch = tid & 7;
    const int b = blockIdx.y, pos0 = blockIdx.x * 32;
    const int ch0 = tch * 64;

    float fr[64];
    const float* fp = fproj + (size_t)(b * NPOS + pos0 + posl) * 512 + ch0;
#pragma unroll
    for (int i = 0; i < 16; i++) {
        const float4 v = *(const float4*)(fp + i * 4);
        fr[i * 4 + 0] = v.x; fr[i * 4 + 1] = v.y;
        fr[i * 4 + 2] = v.z; fr[i * 4 + 3] = v.w;
    }
    for (int k = tid; k < 512; k += 256)
        sWa[(k >> 6) * 65 + (k & 63)] = wa[k];

    for (int t = 0; t < TSTEPS; t++) {
        __syncthreads();
        const float* hrow = hp + (size_t)(t * BB + b) * 512;
        for (int k = tid; k < 512; k += 256)
            sHp[(k >> 6) * 65 + (k & 63)] = hrow[k];
        __syncthreads();
        float s = 0.f;
#pragma unroll
        for (int i = 0; i < 64; i++) {
            const float x = fr[i] + sHp[tch * 65 + i];
            s += fast_tanh(x) * sWa[tch * 65 + i];
        }
        s += __shfl_down_sync(0xffffffffu, s, 4, 8);
        s += __shfl_down_sync(0xffffffffu, s, 2, 8);
        s += __shfl_down_sync(0xffffffffu, s, 1, 8);
        if (tch == 0)
            att[(size_t)(t * BB + b) * NPOS + pos0 + posl] = s;
    }
}

// ---------------------------------------------------------------------------
// Softmax over 256 positions per (t,b). grid 3968, 256 threads
// ---------------------------------------------------------------------------
__global__ __launch_bounds__(256) void softmax_kernel(float* __restrict__ att)
{
    const int row = blockIdx.x, tid = threadIdx.x;
    const int lane = tid & 31, warp = tid >> 5;
    __shared__ float rmax[8], rsum[8];
    const float v = att[(size_t)row * NPOS + tid];
    float m = v;
#pragma unroll
    for (int o = 16; o; o >>= 1) m = fmaxf(m, __shfl_xor_sync(0xffffffffu, m, o));
    if (lane == 0) rmax[warp] = m;
    __syncthreads();
    float M = rmax[0];
#pragma unroll
    for (int i = 1; i < 8; i++) M = fmaxf(M, rmax[i]);
    const float e = __expf(v - M);
    float s = e;
#pragma unroll
    for (int o = 16; o; o >>= 1) s += __shfl_xor_sync(0xffffffffu, s, o);
    if (lane == 0) rsum[warp] = s;
    __syncthreads();
    float S = 0.f;
#pragma unroll
    for (int i = 0; i < 8; i++) S += rsum[i];
    att[(size_t)row * NPOS + tid] = e / S;
}

// ---------------------------------------------------------------------------
// Glimpse: glim[t,b,c] = sum_pos att[t,b,pos] * features[b,pos,c]
// ---------------------------------------------------------------------------
__global__ __launch_bounds__(256) void glimpse_kernel(
    const float* __restrict__ F, const float* __restrict__ att,
    float* __restrict__ glim)
{
    __shared__ float sF[NPOS * 32];
    __shared__ float sA[NPOS];
    __shared__ float sP[8][33];
    const int tid = threadIdx.x;
    const int b = blockIdx.y, ch0 = blockIdx.x * 32;

    for (int idx = tid; idx < NPOS * 32; idx += 256) {
        const int pos = idx >> 5, ch = idx & 31;
        sF[pos * 32 + ch] = F[(size_t)(b * NPOS + pos) * 512 + ch0 + ch];
    }
    const int pg = tid >> 5, ch = tid & 31;

    for (int t = 0; t < TSTEPS; t++) {
        __syncthreads();
        sA[tid] = att[(size_t)(t * BB + b) * NPOS + tid];
        __syncthreads();
        float s = 0.f;
#pragma unroll
        for (int p = 0; p < 32; p++)
            s += sA[pg * 32 + p] * sF[(pg * 32 + p) * 32 + ch];
        sP[pg][ch] = s;
        __syncthreads();
        if (tid < 32) {
            float g = 0.f;
#pragma unroll
            for (int i = 0; i < 8; i++) g += sP[i][tid];
            glim[(size_t)(t * BB + b) * 512 + ch0 + tid] = g;
        }
    }
}

// ---------------------------------------------------------------------------
// Launch
// ---------------------------------------------------------------------------
extern "C" void kernel_launch(void* const* d_in, const int* in_sizes, int n_in,
                              void* d_out, int out_size)
{
    const float* features = (const float*)d_in[0];
    const float* holistic = (const float*)d_in[1];
    const int*   gt       = (const int*)  d_in[2];
    const float* embed_W  = (const float*)d_in[3];
    const float* k0   = (const float*)d_in[4];
    const float* rk0  = (const float*)d_in[5];
    const float* b0   = (const float*)d_in[6];
    const float* k1   = (const float*)d_in[7];
    const float* rk1  = (const float*)d_in[8];
    const float* b1   = (const float*)d_in[9];
    const float* Wh   = (const float*)d_in[10];
    const float* Wf   = (const float*)d_in[11];
    const float* bf   = (const float*)d_in[12];
    const float* wa   = (const float*)d_in[13];
    const float* outW = (const float*)d_in[14];
    const float* outb = (const float*)d_in[15];
    float* out = (float*)d_out;

    float* S = nullptr;
    cudaGetSymbolAddress((void**)&S, g_scratch);

    float* fproj = S + OF_FPROJ;
    float* Ek0   = S + OF_EK0;
    float* h0b[2] = { S + OF_ST,          S + OF_ST + 65536 };
    float* c0b[2] = { S + OF_ST + 131072, S + OF_ST + 196608 };
    float* h1b[2] = { S + OF_ST + 262144, S + OF_ST + 327680 };
    float* c1b[2] = { S + OF_ST + 393216, S + OF_ST + 458752 };
    float* h1all = S + OF_H1ALL;
    float* hp    = S + OF_HP;
    float* att   = S + OF_ATT;
    float* glim  = S + OF_GLIM;
    float* k0t   = S + OF_WT;
    float* rk0t  = S + OF_WT + 1048576;
    float* k1t   = S + OF_WT + 2097152;
    float* rk1t  = S + OF_WT + 3145728;

    // weight reorder (tf32-rounded, gate-interleaved) + embedding table
    reorder_w<<<512, 256>>>(k0,  k0t);
    reorder_w<<<512, 256>>>(rk0, rk0t);
    reorder_w<<<512, 256>>>(k1,  k1t);
    reorder_w<<<512, 256>>>(rk1, rk1t);
    ek0_kernel<<<dim3(8, 112), 256>>>(embed_W, k0, Ek0);

    // Prime the stacked LSTM with the holistic vector (zero state)
    lstm_tc<<<dim3(64, 2), 128>>>(nullptr, nullptr, 0,
        holistic, k0t, nullptr, nullptr, b0, nullptr, h0b[0], c0b[0], nullptr);
    lstm_tc<<<dim3(64, 2), 128>>>(nullptr, nullptr, 0,
        h0b[0], k1t, nullptr, nullptr, b1, nullptr, h1b[0], c1b[0], nullptr);

    // Sequential chain (teacher forcing -> x@k0 is a gather of Ek0)
    for (int t = 0; t < TSTEPS; t++) {
        const int p = t & 1, q = p ^ 1;
        lstm_tc<<<dim3(64, 2), 128>>>(Ek0, gt, t,
            h0b[p], rk0t, nullptr, nullptr, b0, c0b[p], h0b[q], c0b[q], nullptr);
        lstm_tc<<<dim3(64, 2), 128>>>(nullptr, nullptr, 0,
            h0b[q], k1t, h1b[p], rk1t, b1, c1b[p], h1b[q], c1b[q],
            h1all + (size_t)t * BB * 512);
    }

    // Conv (independent of the chain; needed only by att_kernel)
    conv_kernel<<<dim3(4, 256), 256>>>(features, Wf, bf, fproj);

    // Batched epilogue over all 31 steps
    gemm_fused<<<dim3(8, 62), 256>>>(h1all, nullptr, Wh, nullptr, hp, 512, 512, 0);
    att_kernel<<<dim3(8, 128), 256>>>(fproj, hp, wa, att);
    softmax_kernel<<<TSTEPS * BB, 256>>>(att);
    glimpse_kernel<<<dim3(16, 128), 256>>>(features, att, glim);
    gemm_fused<<<dim3(2, 62), 256>>>(h1all, glim, outW, outb, out, NCLS, 1024, 1);
}

// round 9
// speedup vs baseline: 1.4099x; 1.0237x over previous
#include <cuda_runtime.h>
#include <math.h>

// ---------------------------------------------------------------------------
// Problem constants
// ---------------------------------------------------------------------------
#define BB     128
#define TSTEPS 31
#define NCLS   111
#define NPOS   256          // H*W = 8*32
#define CONV_TILES 288      // 4608/16
#define CHAIN_BLOCKS 128u

// ---------------------------------------------------------------------------
// Scratch: one __device__ global array (no runtime allocation allowed)
// ---------------------------------------------------------------------------
#define OF_FPROJ  0u          // 32768*512       = 16777216
#define OF_EK0    16777216u   // 112*2048        = 229376
#define OF_ST     17006592u   // 8 * 65536       = 524288
#define OF_H1ALL  17530880u   // 31*65536        = 2031616
#define OF_HP     19562496u   // 31*65536        = 2031616
#define OF_ATT    21594112u   // 31*128*256      = 1015808
#define OF_GLIM   22609920u   // 31*65536        = 2031616
#define OF_WT     24641536u   // 4 * 512*2048    = 4194304
#define SCRATCH_TOTAL 28835840u
__device__ float g_scratch[SCRATCH_TOTAL];

// grid barrier state (monotone generation; robust across graph replays)
__device__ unsigned g_cnt = 0;
__device__ volatile unsigned g_gen = 0;

// ---------------------------------------------------------------------------
// Helpers
// ---------------------------------------------------------------------------
__device__ __forceinline__ float tf32r(float x) {
    unsigned u; asm("cvt.rna.tf32.f32 %0, %1;" : "=r"(u) : "f"(x));
    return __uint_as_float(u);
}
__device__ __forceinline__ float fast_tanh(float x) {
    float r; asm("tanh.approx.f32 %0, %1;" : "=f"(r) : "f"(x));
    return r;
}
__device__ __forceinline__ void mma_tf32(float* d, const unsigned* a, const unsigned* b) {
    asm volatile(
        "mma.sync.aligned.m16n8k8.row.col.f32.tf32.tf32.f32 "
        "{%0,%1,%2,%3}, {%4,%5,%6,%7}, {%8,%9}, {%0,%1,%2,%3};\n"
        : "+f"(d[0]), "+f"(d[1]), "+f"(d[2]), "+f"(d[3])
        : "r"(a[0]), "r"(a[1]), "r"(a[2]), "r"(a[3]), "r"(b[0]), "r"(b[1]));
}
__device__ __forceinline__ void cp16(float* dst, const float* src, bool v) {
    unsigned d = (unsigned)__cvta_generic_to_shared(dst);
    int sz = v ? 16 : 0;
    asm volatile("cp.async.ca.shared.global [%0], [%1], 16, %2;\n"
                 :: "r"(d), "l"(src), "r"(sz));
}
#define CP_COMMIT() asm volatile("cp.async.commit_group;\n" ::: "memory")
#define CP_WAIT(n)  asm volatile("cp.async.wait_group %0;\n" :: "n"(n) : "memory")

__device__ __forceinline__ void grid_sync() {
    __syncthreads();
    if (threadIdx.x == 0) {
        __threadfence();
        const unsigned gen = g_gen;
        if (atomicAdd(&g_cnt, 1u) == CHAIN_BLOCKS - 1u) {
            g_cnt = 0;
            __threadfence();
            g_gen = gen + 1u;
        } else {
            while (g_gen == gen) { __nanosleep(40); }
        }
        __threadfence();
    }
    __syncthreads();
}

// ---------------------------------------------------------------------------
// Ek0[s][n] = sum_k embed_W[s][k] * k0[k][n] ; row 111 = zeros (SOS). fp32.
// ---------------------------------------------------------------------------
__global__ __launch_bounds__(256) void ek0_kernel(
    const float* __restrict__ eW, const float* __restrict__ k0,
    float* __restrict__ Ek0)
{
    const int n = blockIdx.x * 256 + threadIdx.x;
    const int s = blockIdx.y;
    float a0 = 0.f, a1 = 0.f, a2 = 0.f, a3 = 0.f;
    if (s < 111) {
        const float* e = eW + s * 512;
        for (int k = 0; k < 512; k += 4) {
            a0 += e[k + 0] * k0[(size_t)(k + 0) * 2048 + n];
            a1 += e[k + 1] * k0[(size_t)(k + 1) * 2048 + n];
            a2 += e[k + 2] * k0[(size_t)(k + 2) * 2048 + n];
            a3 += e[k + 3] * k0[(size_t)(k + 3) * 2048 + n];
        }
    }
    Ek0[(size_t)s * 2048 + n] = (a0 + a1) + (a2 + a3);
}

// ---------------------------------------------------------------------------
// Reorder 4 LSTM weight matrices (gate-interleaved, tf32-rounded) in 1 launch
//   out[k][j*4+g] = tf32(in[k][g*512+j]);  grid (512, 4)
// ---------------------------------------------------------------------------
__global__ __launch_bounds__(256) void reorder_w4(
    const float* __restrict__ k0, const float* __restrict__ rk0,
    const float* __restrict__ k1, const float* __restrict__ rk1,
    float* __restrict__ out)
{
    const int k = blockIdx.x, w = blockIdx.y;
    const float* src = (w == 0) ? k0 : (w == 1) ? rk0 : (w == 2) ? k1 : rk1;
    float* dst = out + (size_t)w * 1048576;
    for (int n = threadIdx.x; n < 2048; n += 256) {
        const int g = n & 3, j = n >> 2;
        dst[(size_t)k * 2048 + n] = tf32r(src[(size_t)k * 2048 + g * 512 + j]);
    }
}

// ---------------------------------------------------------------------------
// Conv 3x3 SAME as implicit GEMM, tf32 mma, 3-stage cp.async pipeline.
// M=32768, N=512, K=4608. Block 128x128, BK=16, 256 thr (8 warps 2m x 4n).
// grid (4, 256); dynamic smem.
// ---------------------------------------------------------------------------
#define CONV_SMEM ((3 * 128 * 20 + 3 * 16 * 132) * 4)
__global__ __launch_bounds__(256) void conv_kernel(
    const float* __restrict__ F, const float* __restrict__ Wf,
    const float* __restrict__ bf, float* __restrict__ fproj)
{
    extern __shared__ float sm[];
    float* As = sm;                    // [3][128][20]
    float* Bs = sm + 3 * 128 * 20;     // [3][16][132]

    const int tid = threadIdx.x;
    const int lane = tid & 31, warp = tid >> 5;
    const int wm = warp >> 2, wn = warp & 3;
    const int gid = lane >> 2, tig = lane & 3;
    const int mBase = blockIdx.y * 128, nBase = blockIdx.x * 128;

    const int am = tid >> 1;
    const int ak = (tid & 1) * 8;
    const int gm = mBase + am;
    const int ab = gm >> 8;
    const int ah = (gm >> 5) & 7;
    const int aw = gm & 31;
    const int bk = tid >> 4;
    const int bn = (tid & 15) * 8;

    auto issue = [&](int kt, int s) {
        const int r = kt >> 5;               // kh*3+kw (k-tile never crosses ci)
        const int ci0 = (kt & 31) << 4;
        const int kh = r / 3;
        const int kw = r - kh * 3;
        const int ih = ah + kh - 1, iw = aw + kw - 1;
        const bool v = ((unsigned)ih < 8u) && ((unsigned)iw < 32u);
        const float* p = v ? (F + (((size_t)(ab * 8 + ih) * 32 + iw) << 9) + ci0 + ak) : F;
        float* Ad = As + s * 2560 + am * 20 + ak;
        cp16(Ad,     p,     v);
        cp16(Ad + 4, p + 4, v);
        const float* q = Wf + ((size_t)(kt * 16 + bk)) * 512 + nBase + bn;
        float* Bd = Bs + s * 2112 + bk * 132 + bn;
        cp16(Bd,     q,     true);
        cp16(Bd + 4, q + 4, true);
    };

    float acc[4][4][4];
#pragma unroll
    for (int i = 0; i < 4; i++)
#pragma unroll
        for (int j = 0; j < 4; j++)
#pragma unroll
            for (int c = 0; c < 4; c++) acc[i][j][c] = 0.f;

    issue(0, 0); CP_COMMIT();
    issue(1, 1); CP_COMMIT();
    issue(2, 2); CP_COMMIT();

    for (int kt = 0; kt < CONV_TILES; kt++) {
        const int s = kt % 3;
        if (kt < CONV_TILES - 2)       { CP_WAIT(2); }
        else if (kt == CONV_TILES - 2) { CP_WAIT(1); }
        else                           { CP_WAIT(0); }
        __syncthreads();

        const float* A = As + s * 2560;
        const float* B = Bs + s * 2112;
#pragma unroll
        for (int ks = 0; ks < 16; ks += 8) {
            unsigned afr[4][4], bfr[4][2];
#pragma unroll
            for (int mf = 0; mf < 4; mf++) {
                const int m0 = wm * 64 + mf * 16 + gid;
                afr[mf][0] = __float_as_uint(A[m0 * 20 + ks + tig]);
                afr[mf][1] = __float_as_uint(A[(m0 + 8) * 20 + ks + tig]);
                afr[mf][2] = __float_as_uint(A[m0 * 20 + ks + tig + 4]);
                afr[mf][3] = __float_as_uint(A[(m0 + 8) * 20 + ks + tig + 4]);
            }
#pragma unroll
            for (int nf = 0; nf < 4; nf++) {
                const int n0 = wn * 32 + nf * 8 + gid;
                bfr[nf][0] = __float_as_uint(B[(ks + tig) * 132 + n0]);
                bfr[nf][1] = __float_as_uint(B[(ks + tig + 4) * 132 + n0]);
            }
#pragma unroll
            for (int mf = 0; mf < 4; mf++)
#pragma unroll
                for (int nf = 0; nf < 4; nf++)
                    mma_tf32(acc[mf][nf], afr[mf], bfr[nf]);
        }
        __syncthreads();
        if (kt + 3 < CONV_TILES) { issue(kt + 3, s); CP_COMMIT(); }
    }

#pragma unroll
    for (int mf = 0; mf < 4; mf++) {
        const int row = mBase + wm * 64 + mf * 16 + gid;
#pragma unroll
        for (int nf = 0; nf < 4; nf++) {
            const int col = nBase + wn * 32 + nf * 8 + tig * 2;
            const float bb0 = bf[col], bb1 = bf[col + 1];
            fproj[(size_t)row * 512 + col]           = acc[mf][nf][0] + bb0;
            fproj[(size_t)row * 512 + col + 1]       = acc[mf][nf][1] + bb1;
            fproj[(size_t)(row + 8) * 512 + col]     = acc[mf][nf][2] + bb0;
            fproj[(size_t)(row + 8) * 512 + col + 1] = acc[mf][nf][3] + bb1;
        }
    }
}

// ---------------------------------------------------------------------------
// Persistent LSTM chain: one launch runs all 64 cell phases with grid syncs.
// Per-phase tiling identical to the old lstm_tc: grid (64,2), 128 thr,
// block tile 64m x 32n' (n' = j*4+gate), warp tile 32x16.
// ---------------------------------------------------------------------------
struct ChainSh {
    float As[16][68];
    float Bs[16][40];
    float Zs[64][33];
};

__device__ __noinline__ void lstm_cell_dev(
    ChainSh* sh,
    const float* __restrict__ Ek0, const int* __restrict__ gt, int tstep,
    const float* __restrict__ X1, const float* __restrict__ W1t,
    const float* __restrict__ X2, const float* __restrict__ W2t,
    const float* __restrict__ bias, const float* __restrict__ c_in,
    float* __restrict__ h_out, float* __restrict__ c_out,
    float* __restrict__ h_out2)
{
    const int tid = threadIdx.x;
    const int lane = tid & 31, warp = tid >> 5;
    const int wm = warp >> 1, wn = warp & 1;
    const int gid = lane >> 2, tig = lane & 3;
    const int nBase = blockIdx.x * 32;
    const int mBase = blockIdx.y * 64;

    const int am = tid >> 1, ak = (tid & 1) * 8;   // A: 64 x 16
    const int bk = tid >> 3, bn = (tid & 7) * 4;   // B: 16 x 32

    const int Ktot = X2 ? 1024 : 512;

    float acc[2][2][4];
#pragma unroll
    for (int i = 0; i < 2; i++)
#pragma unroll
        for (int j = 0; j < 2; j++)
#pragma unroll
            for (int c = 0; c < 4; c++) acc[i][j][c] = 0.f;

    float4 aR0, aR1, bR;
    {
        const float* ap = X1 + (size_t)(mBase + am) * 512 + ak;
        aR0 = *(const float4*)ap;
        aR1 = *(const float4*)(ap + 4);
        bR  = *(const float4*)(W1t + (size_t)bk * 2048 + nBase + bn);
    }

    for (int kt = 0; kt < Ktot; kt += 16) {
        __syncthreads();
        sh->As[ak + 0][am] = tf32r(aR0.x); sh->As[ak + 1][am] = tf32r(aR0.y);
        sh->As[ak + 2][am] = tf32r(aR0.z); sh->As[ak + 3][am] = tf32r(aR0.w);
        sh->As[ak + 4][am] = tf32r(aR1.x); sh->As[ak + 5][am] = tf32r(aR1.y);
        sh->As[ak + 6][am] = tf32r(aR1.z); sh->As[ak + 7][am] = tf32r(aR1.w);
        *(float4*)&sh->Bs[bk][bn] = bR;    // weights pre-rounded to tf32
        __syncthreads();

        const int kn = kt + 16;
        if (kn < Ktot) {
            const float* X = (kn < 512) ? X1 : X2;
            const float* W = (kn < 512) ? W1t : W2t;
            const int kk = kn & 511;
            const float* ap = X + (size_t)(mBase + am) * 512 + kk + ak;
            aR0 = *(const float4*)ap;
            aR1 = *(const float4*)(ap + 4);
            bR  = *(const float4*)(W + (size_t)(kk + bk) * 2048 + nBase + bn);
        }

#pragma unroll
        for (int ks = 0; ks < 16; ks += 8) {
            unsigned af[2][4], bf2[2][2];
#pragma unroll
            for (int mf = 0; mf < 2; mf++) {
                const int m0 = wm * 32 + mf * 16 + gid;
                af[mf][0] = __float_as_uint(sh->As[ks + tig][m0]);
                af[mf][1] = __float_as_uint(sh->As[ks + tig][m0 + 8]);
                af[mf][2] = __float_as_uint(sh->As[ks + tig + 4][m0]);
                af[mf][3] = __float_as_uint(sh->As[ks + tig + 4][m0 + 8]);
            }
#pragma unroll
            for (int nf = 0; nf < 2; nf++) {
                const int n0 = wn * 16 + nf * 8 + gid;
                bf2[nf][0] = __float_as_uint(sh->Bs[ks + tig][n0]);
                bf2[nf][1] = __float_as_uint(sh->Bs[ks + tig + 4][n0]);
            }
#pragma unroll
            for (int mf = 0; mf < 2; mf++)
#pragma unroll
                for (int nf = 0; nf < 2; nf++)
                    mma_tf32(acc[mf][nf], af[mf], bf2[nf]);
        }
    }

    __syncthreads();
#pragma unroll
    for (int mf = 0; mf < 2; mf++) {
        const int row = wm * 32 + mf * 16 + gid;
#pragma unroll
        for (int nf = 0; nf < 2; nf++) {
            const int col = wn * 16 + nf * 8 + tig * 2;
            sh->Zs[row][col]         = acc[mf][nf][0];
            sh->Zs[row][col + 1]     = acc[mf][nf][1];
            sh->Zs[row + 8][col]     = acc[mf][nf][2];
            sh->Zs[row + 8][col + 1] = acc[mf][nf][3];
        }
    }
    __syncthreads();

    const int r  = tid >> 1;
    const int j0 = (tid & 1) * 4;
    const int gr = mBase + r;
    int sym = 0;
    if (Ek0) sym = (tstep == 0) ? 111 : gt[gr * TSTEPS + tstep - 1];

#pragma unroll
    for (int jj = 0; jj < 4; jj++) {
        const int j  = j0 + jj;
        const int jg = (nBase >> 2) + j;
        float zi = sh->Zs[r][j * 4 + 0] + bias[jg];
        float zf = sh->Zs[r][j * 4 + 1] + bias[512 + jg];
        float zg = sh->Zs[r][j * 4 + 2] + bias[1024 + jg];
        float zo = sh->Zs[r][j * 4 + 3] + bias[1536 + jg];
        if (Ek0) {
            const float* e = Ek0 + (size_t)sym * 2048;
            zi += e[jg]; zf += e[512 + jg]; zg += e[1024 + jg]; zo += e[1536 + jg];
        }
        const float ci = c_in ? c_in[(size_t)gr * 512 + jg] : 0.f;
        const float si = 1.f / (1.f + expf(-zi));
        const float sf = 1.f / (1.f + expf(-zf));
        const float so = 1.f / (1.f + expf(-zo));
        const float c2 = sf * ci + si * tanhf(zg);
        const float h2 = so * tanhf(c2);
        h_out[(size_t)gr * 512 + jg] = h2;
        c_out[(size_t)gr * 512 + jg] = c2;
        if (h_out2) h_out2[(size_t)gr * 512 + jg] = h2;
    }
}

__global__ __launch_bounds__(128) void lstm_chain(
    const float* __restrict__ Ek0, const int* __restrict__ gt,
    const float* __restrict__ hol,
    const float* __restrict__ k0t, const float* __restrict__ rk0t,
    const float* __restrict__ k1t, const float* __restrict__ rk1t,
    const float* __restrict__ b0, const float* __restrict__ b1,
    float* __restrict__ st, float* __restrict__ h1all)
{
    __shared__ ChainSh sh;
    float* h0b[2] = { st,          st + 65536 };
    float* c0b[2] = { st + 131072, st + 196608 };
    float* h1b[2] = { st + 262144, st + 327680 };
    float* c1b[2] = { st + 393216, st + 458752 };

    // prime with holistic (zero initial state)
    lstm_cell_dev(&sh, nullptr, nullptr, 0, hol, k0t, nullptr, nullptr,
                  b0, nullptr, h0b[0], c0b[0], nullptr);
    grid_sync();
    lstm_cell_dev(&sh, nullptr, nullptr, 0, h0b[0], k1t, nullptr, nullptr,
                  b1, nullptr, h1b[0], c1b[0], nullptr);
    grid_sync();

    for (int t = 0; t < TSTEPS; t++) {
        const int p = t & 1, q = p ^ 1;
        lstm_cell_dev(&sh, Ek0, gt, t, h0b[p], rk0t, nullptr, nullptr,
                      b0, c0b[p], h0b[q], c0b[q], nullptr);
        grid_sync();
        lstm_cell_dev(&sh, nullptr, nullptr, 0, h0b[q], k1t, h1b[p], rk1t,
                      b1, c1b[p], h1b[q], c1b[q],
                      h1all + (size_t)t * BB * 512);
        if (t + 1 < TSTEPS) grid_sync();
    }
}

// ---------------------------------------------------------------------------
// tf32 mma GEMM for hp = h1all @ Wh.  M=3968, N=512, K=512.
// Block 128x128, BK=16, 2-stage cp.async. grid (4, 31), 256 threads.
// ---------------------------------------------------------------------------
__global__ __launch_bounds__(256) void gemm_tc(
    const float* __restrict__ A, const float* __restrict__ W,
    float* __restrict__ C)
{
    __shared__ float As[2][128][20];
    __shared__ float Bs[2][16][132];

    const int tid = threadIdx.x;
    const int lane = tid & 31, warp = tid >> 5;
    const int wm = warp >> 2, wn = warp & 3;
    const int gid = lane >> 2, tig = lane & 3;
    const int mBase = blockIdx.y * 128, nBase = blockIdx.x * 128;

    const int am = tid >> 1;
    const int ak = (tid & 1) * 8;
    const int bk = tid >> 4;
    const int bn = (tid & 15) * 8;

    auto issue = [&](int kt, int s) {
        const float* p = A + (size_t)(mBase + am) * 512 + kt * 16 + ak;
        cp16(&As[s][am][ak],     p,     true);
        cp16(&As[s][am][ak + 4], p + 4, true);
        const float* q = W + (size_t)(kt * 16 + bk) * 512 + nBase + bn;
        cp16(&Bs[s][bk][bn],     q,     true);
        cp16(&Bs[s][bk][bn + 4], q + 4, true);
    };

    float acc[4][4][4];
#pragma unroll
    for (int i = 0; i < 4; i++)
#pragma unroll
        for (int j = 0; j < 4; j++)
#pragma unroll
            for (int c = 0; c < 4; c++) acc[i][j][c] = 0.f;

    issue(0, 0); CP_COMMIT();
    issue(1, 1); CP_COMMIT();

    const int NT = 32;
    for (int kt = 0; kt < NT; kt++) {
        const int s = kt & 1;
        if (kt + 1 < NT) { CP_WAIT(1); } else { CP_WAIT(0); }
        __syncthreads();
#pragma unroll
        for (int ks = 0; ks < 16; ks += 8) {
            unsigned afr[4][4], bfr[4][2];
#pragma unroll
            for (int mf = 0; mf < 4; mf++) {
                const int m0 = wm * 64 + mf * 16 + gid;
                afr[mf][0] = __float_as_uint(As[s][m0][ks + tig]);
                afr[mf][1] = __float_as_uint(As[s][m0 + 8][ks + tig]);
                afr[mf][2] = __float_as_uint(As[s][m0][ks + tig + 4]);
                afr[mf][3] = __float_as_uint(As[s][m0 + 8][ks + tig + 4]);
            }
#pragma unroll
            for (int nf = 0; nf < 4; nf++) {
                const int n0 = wn * 32 + nf * 8 + gid;
                bfr[nf][0] = __float_as_uint(Bs[s][ks + tig][n0]);
                bfr[nf][1] = __float_as_uint(Bs[s][ks + tig + 4][n0]);
            }
#pragma unroll
            for (int mf = 0; mf < 4; mf++)
#pragma unroll
                for (int nf = 0; nf < 4; nf++)
                    mma_tf32(acc[mf][nf], afr[mf], bfr[nf]);
        }
        __syncthreads();
        if (kt + 2 < NT) { issue(kt + 2, s); CP_COMMIT(); }
    }

#pragma unroll
    for (int mf = 0; mf < 4; mf++) {
        const int row = mBase + wm * 64 + mf * 16 + gid;
#pragma unroll
        for (int nf = 0; nf < 4; nf++) {
            const int col = nBase + wn * 32 + nf * 8 + tig * 2;
            C[(size_t)row * 512 + col]           = acc[mf][nf][0];
            C[(size_t)row * 512 + col + 1]       = acc[mf][nf][1];
            C[(size_t)(row + 8) * 512 + col]     = acc[mf][nf][2];
            C[(size_t)(row + 8) * 512 + col + 1] = acc[mf][nf][3];
        }
    }
}

// ---------------------------------------------------------------------------
// fp32 GEMM (logits): C = [A1|A2] @ W + bias, remapped out layout.
// ---------------------------------------------------------------------------
__global__ __launch_bounds__(256) void gemm_fused(
    const float* __restrict__ A1, const float* __restrict__ A2,
    const float* __restrict__ W, const float* __restrict__ bias,
    float* __restrict__ C, int N, int K)
{
    __shared__ float sA[16][65];
    __shared__ float sB[16][68];
    const int tid = threadIdx.x;
    const int tx = tid & 15, ty = tid >> 4;
    const int mBase = blockIdx.y * 64, nBase = blockIdx.x * 64;

    const int lam = tid >> 2, lak = (tid & 3) * 4;
    const int lbk = tid >> 4, lbn = (tid & 15) * 4;

    float acc[4][4];
#pragma unroll
    for (int i = 0; i < 4; i++)
#pragma unroll
        for (int j = 0; j < 4; j++) acc[i][j] = 0.f;

    for (int k0 = 0; k0 < K; k0 += 16) {
        float av[4], bv[4];
#pragma unroll
        for (int i = 0; i < 4; i++) {
            const int kk = k0 + lak + i;
            av[i] = (kk < 512) ? A1[(size_t)(mBase + lam) * 512 + kk]
                               : A2[(size_t)(mBase + lam) * 512 + kk - 512];
        }
#pragma unroll
        for (int i = 0; i < 4; i++) {
            const int nn = nBase + lbn + i;
            bv[i] = (nn < N) ? W[(size_t)(k0 + lbk) * N + nn] : 0.f;
        }
        __syncthreads();
#pragma unroll
        for (int i = 0; i < 4; i++) sA[lak + i][lam] = av[i];
#pragma unroll
        for (int i = 0; i < 4; i++) sB[lbk][lbn + i] = bv[i];
        __syncthreads();
#pragma unroll
        for (int kk = 0; kk < 16; kk++) {
            float a[4], b[4];
#pragma unroll
            for (int i = 0; i < 4; i++) a[i] = sA[kk][ty * 4 + i];
#pragma unroll
            for (int j = 0; j < 4; j++) b[j] = sB[kk][tx * 4 + j];
#pragma unroll
            for (int i = 0; i < 4; i++)
#pragma unroll
                for (int j = 0; j < 4; j++) acc[i][j] += a[i] * b[j];
        }
    }

#pragma unroll
    for (int i = 0; i < 4; i++) {
        const int row = mBase + ty * 4 + i;
#pragma unroll
        for (int j = 0; j < 4; j++) {
            const int col = nBase + tx * 4 + j;
            if (col < N) {
                const float v = acc[i][j] + bias[col];
                const int t = row >> 7, b = row & 127;
                C[(size_t)(b * TSTEPS + t) * NCLS + col] = v;
            }
        }
    }
}

// ---------------------------------------------------------------------------
// Attention logits: att[t,b,pos] = sum_ch tanh(fproj[b,pos,ch]+hp[t,b,ch])*wa[ch]
// fproj register-resident (read once). grid (8 pos-chunks, 128 b), 256 thr
// ---------------------------------------------------------------------------
__global__ __launch_bounds__(256) void att_kernel(
    const float* __restrict__ fproj, const float* __restrict__ hp,
    const float* __restrict__ wa, float* __restrict__ att)
{
    __shared__ float sHp[8 * 65];
    __shared__ float sWa[8 * 65];
    const int tid = threadIdx.x;
    const int posl = tid >> 3, tch = tid & 7;
    const int b = blockIdx.y, pos0 = blockIdx.x * 32;
    const int ch0 = tch * 64;

    float fr[64];
    const float* fp = fproj + (size_t)(b * NPOS + pos0 + posl) * 512 + ch0;
#pragma unroll
    for (int i = 0; i < 16; i++) {
        const float4 v = *(const float4*)(fp + i * 4);
        fr[i * 4 + 0] = v.x; fr[i * 4 + 1] = v.y;
        fr[i * 4 + 2] = v.z; fr[i * 4 + 3] = v.w;
    }
    for (int k = tid; k < 512; k += 256)
        sWa[(k >> 6) * 65 + (k & 63)] = wa[k];

    for (int t = 0; t < TSTEPS; t++) {
        __syncthreads();
        const float* hrow = hp + (size_t)(t * BB + b) * 512;
        for (int k = tid; k < 512; k += 256)
            sHp[(k >> 6) * 65 + (k & 63)] = hrow[k];
        __syncthreads();
        float s = 0.f;
#pragma unroll
        for (int i = 0; i < 64; i++) {
            const float x = fr[i] + sHp[tch * 65 + i];
            s += fast_tanh(x) * sWa[tch * 65 + i];
        }
        s += __shfl_down_sync(0xffffffffu, s, 4, 8);
        s += __shfl_down_sync(0xffffffffu, s, 2, 8);
        s += __shfl_down_sync(0xffffffffu, s, 1, 8);
        if (tch == 0)
            att[(size_t)(t * BB + b) * NPOS + pos0 + posl] = s;
    }
}

// ---------------------------------------------------------------------------
// Softmax over 256 positions per (t,b). grid 3968, 256 threads
// ---------------------------------------------------------------------------
__global__ __launch_bounds__(256) void softmax_kernel(float* __restrict__ att)
{
    const int row = blockIdx.x, tid = threadIdx.x;
    const int lane = tid & 31, warp = tid >> 5;
    __shared__ float rmax[8], rsum[8];
    const float v = att[(size_t)row * NPOS + tid];
    float m = v;
#pragma unroll
    for (int o = 16; o; o >>= 1) m = fmaxf(m, __shfl_xor_sync(0xffffffffu, m, o));
    if (lane == 0) rmax[warp] = m;
    __syncthreads();
    float M = rmax[0];
#pragma unroll
    for (int i = 1; i < 8; i++) M = fmaxf(M, rmax[i]);
    const float e = __expf(v - M);
    float s = e;
#pragma unroll
    for (int o = 16; o; o >>= 1) s += __shfl_xor_sync(0xffffffffu, s, o);
    if (lane == 0) rsum[warp] = s;
    __syncthreads();
    float S = 0.f;
#pragma unroll
    for (int i = 0; i < 8; i++) S += rsum[i];
    att[(size_t)row * NPOS + tid] = e / S;
}

// ---------------------------------------------------------------------------
// Glimpse: glim[t,b,c] = sum_pos att[t,b,pos] * features[b,pos,c]
// ---------------------------------------------------------------------------
__global__ __launch_bounds__(256) void glimpse_kernel(
    const float* __restrict__ F, const float* __restrict__ att,
    float* __restrict__ glim)
{
    __shared__ float sF[NPOS * 32];
    __shared__ float sA[NPOS];
    __shared__ float sP[8][33];
    const int tid = threadIdx.x;
    const int b = blockIdx.y, ch0 = blockIdx.x * 32;

    for (int idx = tid; idx < NPOS * 32; idx += 256) {
        const int pos = idx >> 5, ch = idx & 31;
        sF[pos * 32 + ch] = F[(size_t)(b * NPOS + pos) * 512 + ch0 + ch];
    }
    const int pg = tid >> 5, ch = tid & 31;

    for (int t = 0; t < TSTEPS; t++) {
        __syncthreads();
        sA[tid] = att[(size_t)(t * BB + b) * NPOS + tid];
        __syncthreads();
        float s = 0.f;
#pragma unroll
        for (int p = 0; p < 32; p++)
            s += sA[pg * 32 + p] * sF[(pg * 32 + p) * 32 + ch];
        sP[pg][ch] = s;
        __syncthreads();
        if (tid < 32) {
            float g = 0.f;
#pragma unroll
            for (int i = 0; i < 8; i++) g += sP[i][tid];
            glim[(size_t)(t * BB + b) * 512 + ch0 + tid] = g;
        }
    }
}

// ---------------------------------------------------------------------------
// Launch
// ---------------------------------------------------------------------------
extern "C" void kernel_launch(void* const* d_in, const int* in_sizes, int n_in,
                              void* d_out, int out_size)
{
    const float* features = (const float*)d_in[0];
    const float* holistic = (const float*)d_in[1];
    const int*   gt       = (const int*)  d_in[2];
    const float* embed_W  = (const float*)d_in[3];
    const float* k0   = (const float*)d_in[4];
    const float* rk0  = (const float*)d_in[5];
    const float* b0   = (const float*)d_in[6];
    const float* k1   = (const float*)d_in[7];
    const float* rk1  = (const float*)d_in[8];
    const float* b1   = (const float*)d_in[9];
    const float* Wh   = (const float*)d_in[10];
    const float* Wf   = (const float*)d_in[11];
    const float* bf   = (const float*)d_in[12];
    const float* wa   = (const float*)d_in[13];
    const float* outW = (const float*)d_in[14];
    const float* outb = (const float*)d_in[15];
    float* out = (float*)d_out;

    float* S = nullptr;
    cudaGetSymbolAddress((void**)&S, g_scratch);

    float* fproj = S + OF_FPROJ;
    float* Ek0   = S + OF_EK0;
    float* st    = S + OF_ST;
    float* h1all = S + OF_H1ALL;
    float* hp    = S + OF_HP;
    float* att   = S + OF_ATT;
    float* glim  = S + OF_GLIM;
    float* k0t   = S + OF_WT;
    float* rk0t  = S + OF_WT + 1048576;
    float* k1t   = S + OF_WT + 2097152;
    float* rk1t  = S + OF_WT + 3145728;

    cudaFuncSetAttribute(conv_kernel,
        cudaFuncAttributeMaxDynamicSharedMemorySize, CONV_SMEM);

    // prep (1 launch) + embedding table
    reorder_w4<<<dim3(512, 4), 256>>>(k0, rk0, k1, rk1, k0t);
    ek0_kernel<<<dim3(8, 112), 256>>>(embed_W, k0, Ek0);

    // big conv (independent of the chain; feeds only att_kernel)
    conv_kernel<<<dim3(4, 256), 256, CONV_SMEM>>>(features, Wf, bf, fproj);

    // whole LSTM chain in ONE persistent launch (grid barrier between phases)
    lstm_chain<<<dim3(64, 2), 128>>>(Ek0, gt, holistic,
        k0t, rk0t, k1t, rk1t, b0, b1, st, h1all);

    // batched epilogue over all 31 steps
    gemm_tc<<<dim3(4, 31), 256>>>(h1all, Wh, hp);
    att_kernel<<<dim3(8, 128), 256>>>(fproj, hp, wa, att);
    softmax_kernel<<<TSTEPS * BB, 256>>>(att);
    glimpse_kernel<<<dim3(16, 128), 256>>>(features, att, glim);
    gemm_fused<<<dim3(2, 62), 256>>>(h1all, glim, outW, outb, out, NCLS, 1024);
}

// round 12
// speedup vs baseline: 2.1094x; 1.4961x over previous
#include <cuda_runtime.h>
#include <math.h>

// ---------------------------------------------------------------------------
// Problem constants
// ---------------------------------------------------------------------------
#define BB     128
#define TSTEPS 31
#define NCLS   111
#define NPOS   256          // H*W = 8*32
#define CONV_TILES 288      // 4608/16
#define CHAIN_BLOCKS 64u

// ---------------------------------------------------------------------------
// Scratch: one __device__ global array (no runtime allocation allowed)
// ---------------------------------------------------------------------------
#define OF_FPROJ  0u          // 32768*512       = 16777216
#define OF_EK0    16777216u   // 112*2048        = 229376
#define OF_ST     17006592u   // 8 * 65536       = 524288
#define OF_H1ALL  17530880u   // 31*65536        = 2031616
#define OF_HP     19562496u   // 31*65536        = 2031616
#define OF_ATT    21594112u   // 31*128*256      = 1015808
#define OF_GLIM   22609920u   // 31*65536        = 2031616
#define OF_WT     24641536u   // 4 * 512*2048    = 4194304
#define SCRATCH_TOTAL 28835840u
__device__ float g_scratch[SCRATCH_TOTAL];

// grid barrier state (monotone generation; robust across graph replays)
__device__ unsigned g_cnt = 0;
__device__ volatile unsigned g_gen = 0;

// ---------------------------------------------------------------------------
// Helpers
// ---------------------------------------------------------------------------
__device__ __forceinline__ float tf32r(float x) {
    unsigned u; asm("cvt.rna.tf32.f32 %0, %1;" : "=r"(u) : "f"(x));
    return __uint_as_float(u);
}
__device__ __forceinline__ float fast_tanh(float x) {
    float r; asm("tanh.approx.f32 %0, %1;" : "=f"(r) : "f"(x));
    return r;
}
__device__ __forceinline__ void mma_tf32(float* d, const unsigned* a, const unsigned* b) {
    asm volatile(
        "mma.sync.aligned.m16n8k8.row.col.f32.tf32.tf32.f32 "
        "{%0,%1,%2,%3}, {%4,%5,%6,%7}, {%8,%9}, {%0,%1,%2,%3};\n"
        : "+f"(d[0]), "+f"(d[1]), "+f"(d[2]), "+f"(d[3])
        : "r"(a[0]), "r"(a[1]), "r"(a[2]), "r"(a[3]), "r"(b[0]), "r"(b[1]));
}
__device__ __forceinline__ void cp16(float* dst, const float* src, bool v) {
    unsigned d = (unsigned)__cvta_generic_to_shared(dst);
    int sz = v ? 16 : 0;
    asm volatile("cp.async.ca.shared.global [%0], [%1], 16, %2;\n"
                 :: "r"(d), "l"(src), "r"(sz));
}
#define CP_COMMIT() asm volatile("cp.async.commit_group;\n" ::: "memory")
#define CP_WAIT(n)  asm volatile("cp.async.wait_group %0;\n" :: "n"(n) : "memory")

__device__ __forceinline__ void grid_sync() {
    __syncthreads();
    if (threadIdx.x == 0) {
        __threadfence();
        const unsigned gen = g_gen;
        if (atomicAdd(&g_cnt, 1u) == CHAIN_BLOCKS - 1u) {
            g_cnt = 0;
            __threadfence();
            g_gen = gen + 1u;
        } else {
            while (g_gen == gen) { __nanosleep(40); }
        }
        __threadfence();
    }
    __syncthreads();
}

// ---------------------------------------------------------------------------
// Ek0[s][n] = sum_k embed_W[s][k] * k0[k][n] ; row 111 = zeros (SOS). fp32.
// ---------------------------------------------------------------------------
__global__ __launch_bounds__(256) void ek0_kernel(
    const float* __restrict__ eW, const float* __restrict__ k0,
    float* __restrict__ Ek0)
{
    const int n = blockIdx.x * 256 + threadIdx.x;
    const int s = blockIdx.y;
    float a0 = 0.f, a1 = 0.f, a2 = 0.f, a3 = 0.f;
    if (s < 111) {
        const float* e = eW + s * 512;
        for (int k = 0; k < 512; k += 4) {
            a0 += e[k + 0] * k0[(size_t)(k + 0) * 2048 + n];
            a1 += e[k + 1] * k0[(size_t)(k + 1) * 2048 + n];
            a2 += e[k + 2] * k0[(size_t)(k + 2) * 2048 + n];
            a3 += e[k + 3] * k0[(size_t)(k + 3) * 2048 + n];
        }
    }
    Ek0[(size_t)s * 2048 + n] = (a0 + a1) + (a2 + a3);
}

// ---------------------------------------------------------------------------
// Reorder 4 LSTM weight matrices (gate-interleaved, tf32-rounded) in 1 launch
//   out[k][j*4+g] = tf32(in[k][g*512+j]);  grid (512, 4)
// ---------------------------------------------------------------------------
__global__ __launch_bounds__(256) void reorder_w4(
    const float* __restrict__ k0, const float* __restrict__ rk0,
    const float* __restrict__ k1, const float* __restrict__ rk1,
    float* __restrict__ out)
{
    const int k = blockIdx.x, w = blockIdx.y;
    const float* src = (w == 0) ? k0 : (w == 1) ? rk0 : (w == 2) ? k1 : rk1;
    float* dst = out + (size_t)w * 1048576;
    for (int n = threadIdx.x; n < 2048; n += 256) {
        const int g = n & 3, j = n >> 2;
        dst[(size_t)k * 2048 + n] = tf32r(src[(size_t)k * 2048 + g * 512 + j]);
    }
}

// ---------------------------------------------------------------------------
// Conv device body: 3x3 SAME implicit GEMM, tf32 mma, 3-stage cp.async.
// M=32768, N=512, K=4608. Tile 128x128, BK=16, 256 thr (8 warps 2m x 4n).
// cid in [0,1024): nBase = (cid&3)*128, mBase = (cid>>2)*128.
// smem: As [3][128][20] + Bs [3][16][132] = 56064 bytes.
// ---------------------------------------------------------------------------
#define CONV_SMEM ((3 * 128 * 20 + 3 * 16 * 132) * 4)
__device__ void conv_body(
    float* sm, int cid,
    const float* __restrict__ F, const float* __restrict__ Wf,
    const float* __restrict__ bf, float* __restrict__ fproj)
{
    float* As = sm;                    // [3][128][20]
    float* Bs = sm + 3 * 128 * 20;     // [3][16][132]

    const int tid = threadIdx.x;
    const int lane = tid & 31, warp = tid >> 5;
    const int wm = warp >> 2, wn = warp & 3;
    const int gid = lane >> 2, tig = lane & 3;
    const int nBase = (cid & 3) * 128;
    const int mBase = (cid >> 2) * 128;

    const int am = tid >> 1;
    const int ak = (tid & 1) * 8;
    const int gm = mBase + am;
    const int ab = gm >> 8;
    const int ah = (gm >> 5) & 7;
    const int aw = gm & 31;
    const int bk = tid >> 4;
    const int bn = (tid & 15) * 8;

    auto issue = [&](int kt, int s) {
        const int r = kt >> 5;               // kh*3+kw (k-tile never crosses ci)
        const int ci0 = (kt & 31) << 4;
        const int kh = r / 3;
        const int kw = r - kh * 3;
        const int ih = ah + kh - 1, iw = aw + kw - 1;
        const bool v = ((unsigned)ih < 8u) && ((unsigned)iw < 32u);
        const float* p = v ? (F + (((size_t)(ab * 8 + ih) * 32 + iw) << 9) + ci0 + ak) : F;
        float* Ad = As + s * 2560 + am * 20 + ak;
        cp16(Ad,     p,     v);
        cp16(Ad + 4, p + 4, v);
        const float* q = Wf + ((size_t)(kt * 16 + bk)) * 512 + nBase + bn;
        float* Bd = Bs + s * 2112 + bk * 132 + bn;
        cp16(Bd,     q,     true);
        cp16(Bd + 4, q + 4, true);
    };

    float acc[4][4][4];
#pragma unroll
    for (int i = 0; i < 4; i++)
#pragma unroll
        for (int j = 0; j < 4; j++)
#pragma unroll
            for (int c = 0; c < 4; c++) acc[i][j][c] = 0.f;

    issue(0, 0); CP_COMMIT();
    issue(1, 1); CP_COMMIT();
    issue(2, 2); CP_COMMIT();

    for (int kt = 0; kt < CONV_TILES; kt++) {
        const int s = kt % 3;
        if (kt < CONV_TILES - 2)       { CP_WAIT(2); }
        else if (kt == CONV_TILES - 2) { CP_WAIT(1); }
        else                           { CP_WAIT(0); }
        __syncthreads();

        const float* A = As + s * 2560;
        const float* B = Bs + s * 2112;
#pragma unroll
        for (int ks = 0; ks < 16; ks += 8) {
            unsigned afr[4][4], bfr[4][2];
#pragma unroll
            for (int mf = 0; mf < 4; mf++) {
                const int m0 = wm * 64 + mf * 16 + gid;
                afr[mf][0] = __float_as_uint(A[m0 * 20 + ks + tig]);
                afr[mf][1] = __float_as_uint(A[(m0 + 8) * 20 + ks + tig]);
                afr[mf][2] = __float_as_uint(A[m0 * 20 + ks + tig + 4]);
                afr[mf][3] = __float_as_uint(A[(m0 + 8) * 20 + ks + tig + 4]);
            }
#pragma unroll
            for (int nf = 0; nf < 4; nf++) {
                const int n0 = wn * 32 + nf * 8 + gid;
                bfr[nf][0] = __float_as_uint(B[(ks + tig) * 132 + n0]);
                bfr[nf][1] = __float_as_uint(B[(ks + tig + 4) * 132 + n0]);
            }
#pragma unroll
            for (int mf = 0; mf < 4; mf++)
#pragma unroll
                for (int nf = 0; nf < 4; nf++)
                    mma_tf32(acc[mf][nf], afr[mf], bfr[nf]);
        }
        __syncthreads();
        if (kt + 3 < CONV_TILES) { issue(kt + 3, s); CP_COMMIT(); }
    }

#pragma unroll
    for (int mf = 0; mf < 4; mf++) {
        const int row = mBase + wm * 64 + mf * 16 + gid;
#pragma unroll
        for (int nf = 0; nf < 4; nf++) {
            const int col = nBase + wn * 32 + nf * 8 + tig * 2;
            const float bb0 = bf[col], bb1 = bf[col + 1];
            fproj[(size_t)row * 512 + col]           = acc[mf][nf][0] + bb0;
            fproj[(size_t)row * 512 + col + 1]       = acc[mf][nf][1] + bb1;
            fproj[(size_t)(row + 8) * 512 + col]     = acc[mf][nf][2] + bb0;
            fproj[(size_t)(row + 8) * 512 + col + 1] = acc[mf][nf][3] + bb1;
        }
    }
}

// ---------------------------------------------------------------------------
// LSTM cell for the chain: 256 threads, block tile 64m x 64n' (n' = j*4+gate).
// 8 warps (2m x 4n), warp tile 32x16. Same mma order as R9 -> identical bits.
// ---------------------------------------------------------------------------
struct ChainSh2 {
    float As[16][68];   // [k][m]
    float Bs[16][72];   // [k][n'] pitch 72 floats = 288B (16B aligned rows)
    float Zs[64][68];
};

__device__ void lstm_cell2(
    ChainSh2* sh, int nTile, int mTile,
    const float* __restrict__ Ek0, const int* __restrict__ gt, int tstep,
    const float* __restrict__ X1, const float* __restrict__ W1t,
    const float* __restrict__ X2, const float* __restrict__ W2t,
    const float* __restrict__ bias, const float* __restrict__ c_in,
    float* __restrict__ h_out, float* __restrict__ c_out,
    float* __restrict__ h_out2)
{
    const int tid = threadIdx.x;
    const int lane = tid & 31, warp = tid >> 5;
    const int wm = warp >> 2, wn = warp & 3;
    const int gid = lane >> 2, tig = lane & 3;
    const int nBase = nTile * 64;
    const int mBase = mTile * 64;

    const int am = tid >> 2, ak = (tid & 3) * 4;   // A: 64 x 16, 1 float4/thr
    const int bk = tid >> 4, bn = (tid & 15) * 4;  // B: 16 x 64, 1 float4/thr

    const int Ktot = X2 ? 1024 : 512;

    float acc[2][2][4];
#pragma unroll
    for (int i = 0; i < 2; i++)
#pragma unroll
        for (int j = 0; j < 2; j++)
#pragma unroll
            for (int c = 0; c < 4; c++) acc[i][j][c] = 0.f;

    float4 aR, bR;
    aR = *(const float4*)(X1 + (size_t)(mBase + am) * 512 + ak);
    bR = *(const float4*)(W1t + (size_t)bk * 2048 + nBase + bn);

    for (int kt = 0; kt < Ktot; kt += 16) {
        __syncthreads();
        sh->As[ak + 0][am] = tf32r(aR.x);
        sh->As[ak + 1][am] = tf32r(aR.y);
        sh->As[ak + 2][am] = tf32r(aR.z);
        sh->As[ak + 3][am] = tf32r(aR.w);
        *(float4*)&sh->Bs[bk][bn] = bR;    // weights pre-rounded to tf32
        __syncthreads();

        const int kn = kt + 16;
        if (kn < Ktot) {
            const float* X = (kn < 512) ? X1 : X2;
            const float* W = (kn < 512) ? W1t : W2t;
            const int kk = kn & 511;
            aR = *(const float4*)(X + (size_t)(mBase + am) * 512 + kk + ak);
            bR = *(const float4*)(W + (size_t)(kk + bk) * 2048 + nBase + bn);
        }

#pragma unroll
        for (int ks = 0; ks < 16; ks += 8) {
            unsigned af[2][4], bf2[2][2];
#pragma unroll
            for (int mf = 0; mf < 2; mf++) {
                const int m0 = wm * 32 + mf * 16 + gid;
                af[mf][0] = __float_as_uint(sh->As[ks + tig][m0]);
                af[mf][1] = __float_as_uint(sh->As[ks + tig][m0 + 8]);
                af[mf][2] = __float_as_uint(sh->As[ks + tig + 4][m0]);
                af[mf][3] = __float_as_uint(sh->As[ks + tig + 4][m0 + 8]);
            }
#pragma unroll
            for (int nf = 0; nf < 2; nf++) {
                const int n0 = wn * 16 + nf * 8 + gid;
                bf2[nf][0] = __float_as_uint(sh->Bs[ks + tig][n0]);
                bf2[nf][1] = __float_as_uint(sh->Bs[ks + tig + 4][n0]);
            }
#pragma unroll
            for (int mf = 0; mf < 2; mf++)
#pragma unroll
                for (int nf = 0; nf < 2; nf++)
                    mma_tf32(acc[mf][nf], af[mf], bf2[nf]);
        }
    }

    __syncthreads();
#pragma unroll
    for (int mf = 0; mf < 2; mf++) {
        const int row = wm * 32 + mf * 16 + gid;
#pragma unroll
        for (int nf = 0; nf < 2; nf++) {
            const int col = wn * 16 + nf * 8 + tig * 2;
            sh->Zs[row][col]         = acc[mf][nf][0];
            sh->Zs[row][col + 1]     = acc[mf][nf][1];
            sh->Zs[row + 8][col]     = acc[mf][nf][2];
            sh->Zs[row + 8][col + 1] = acc[mf][nf][3];
        }
    }
    __syncthreads();

    // Fused gating: 64 rows x 16 j per block; thread -> (row, 4 j's)
    const int r  = tid >> 2;
    const int j0 = (tid & 3) * 4;
    const int gr = mBase + r;
    int sym = 0;
    if (Ek0) sym = (tstep == 0) ? 111 : gt[gr * TSTEPS + tstep - 1];

#pragma unroll
    for (int jj = 0; jj < 4; jj++) {
        const int j  = j0 + jj;
        const int jg = nTile * 16 + j;
        float zi = sh->Zs[r][j * 4 + 0] + bias[jg];
        float zf = sh->Zs[r][j * 4 + 1] + bias[512 + jg];
        float zg = sh->Zs[r][j * 4 + 2] + bias[1024 + jg];
        float zo = sh->Zs[r][j * 4 + 3] + bias[1536 + jg];
        if (Ek0) {
            const float* e = Ek0 + (size_t)sym * 2048;
            zi += e[jg]; zf += e[512 + jg]; zg += e[1024 + jg]; zo += e[1536 + jg];
        }
        const float ci = c_in ? c_in[(size_t)gr * 512 + jg] : 0.f;
        const float si = 1.f / (1.f + expf(-zi));
        const float sf = 1.f / (1.f + expf(-zf));
        const float so = 1.f / (1.f + expf(-zo));
        const float c2 = sf * ci + si * tanhf(zg);
        const float h2 = so * tanhf(c2);
        h_out[(size_t)gr * 512 + jg] = h2;
        c_out[(size_t)gr * 512 + jg] = c2;
        if (h_out2) h_out2[(size_t)gr * 512 + jg] = h2;
    }
}

__device__ void chain_body(
    ChainSh2* sh, int cbid,
    const float* __restrict__ Ek0, const int* __restrict__ gt,
    const float* __restrict__ hol,
    const float* __restrict__ k0t, const float* __restrict__ rk0t,
    const float* __restrict__ k1t, const float* __restrict__ rk1t,
    const float* __restrict__ b0, const float* __restrict__ b1,
    float* __restrict__ st, float* __restrict__ h1all)
{
    const int nTile = cbid & 31;     // 32 n'-tiles of 64
    const int mTile = cbid >> 5;     // 2 m-tiles of 64
    float* h0b[2] = { st,          st + 65536 };
    float* c0b[2] = { st + 131072, st + 196608 };
    float* h1b[2] = { st + 262144, st + 327680 };
    float* c1b[2] = { st + 393216, st + 458752 };

    // prime with holistic (zero initial state)
    lstm_cell2(sh, nTile, mTile, nullptr, nullptr, 0, hol, k0t, nullptr, nullptr,
               b0, nullptr, h0b[0], c0b[0], nullptr);
    grid_sync();
    lstm_cell2(sh, nTile, mTile, nullptr, nullptr, 0, h0b[0], k1t, nullptr, nullptr,
               b1, nullptr, h1b[0], c1b[0], nullptr);
    grid_sync();

    for (int t = 0; t < TSTEPS; t++) {
        const int p = t & 1, q = p ^ 1;
        lstm_cell2(sh, nTile, mTile, Ek0, gt, t, h0b[p], rk0t, nullptr, nullptr,
                   b0, c0b[p], h0b[q], c0b[q], nullptr);
        grid_sync();
        lstm_cell2(sh, nTile, mTile, nullptr, nullptr, 0, h0b[q], k1t, h1b[p], rk1t,
                   b1, c1b[p], h1b[q], c1b[q],
                   h1all + (size_t)t * BB * 512);
        if (t + 1 < TSTEPS) grid_sync();
    }
}

// ---------------------------------------------------------------------------
// Fused kernel: bids 0..63 run the persistent LSTM chain (wave-1 resident ->
// grid barrier safe); bids 64..1087 run the conv. Independent workloads
// overlap on the chip instead of serializing through the graph.
// ---------------------------------------------------------------------------
__global__ __launch_bounds__(256, 2) void fused_conv_chain(
    const float* __restrict__ F, const float* __restrict__ Wf,
    const float* __restrict__ bf, float* __restrict__ fproj,
    const float* __restrict__ Ek0, const int* __restrict__ gt,
    const float* __restrict__ hol,
    const float* __restrict__ k0t, const float* __restrict__ rk0t,
    const float* __restrict__ k1t, const float* __restrict__ rk1t,
    const float* __restrict__ b0, const float* __restrict__ b1,
    float* __restrict__ st, float* __restrict__ h1all)
{
    extern __shared__ float smx[];
    if (blockIdx.x < (int)CHAIN_BLOCKS) {
        chain_body((ChainSh2*)smx, blockIdx.x, Ek0, gt, hol,
                   k0t, rk0t, k1t, rk1t, b0, b1, st, h1all);
    } else {
        conv_body(smx, blockIdx.x - (int)CHAIN_BLOCKS, F, Wf, bf, fproj);
    }
}

// ---------------------------------------------------------------------------
// tf32 mma GEMM for hp = h1all @ Wh.  M=3968, N=512, K=512.
// ---------------------------------------------------------------------------
__global__ __launch_bounds__(256) void gemm_tc(
    const float* __restrict__ A, const float* __restrict__ W,
    float* __restrict__ C)
{
    __shared__ float As[2][128][20];
    __shared__ float Bs[2][16][132];

    const int tid = threadIdx.x;
    const int lane = tid & 31, warp = tid >> 5;
    const int wm = warp >> 2, wn = warp & 3;
    const int gid = lane >> 2, tig = lane & 3;
    const int mBase = blockIdx.y * 128, nBase = blockIdx.x * 128;

    const int am = tid >> 1;
    const int ak = (tid & 1) * 8;
    const int bk = tid >> 4;
    const int bn = (tid & 15) * 8;

    auto issue = [&](int kt, int s) {
        const float* p = A + (size_t)(mBase + am) * 512 + kt * 16 + ak;
        cp16(&As[s][am][ak],     p,     true);
        cp16(&As[s][am][ak + 4], p + 4, true);
        const float* q = W + (size_t)(kt * 16 + bk) * 512 + nBase + bn;
        cp16(&Bs[s][bk][bn],     q,     true);
        cp16(&Bs[s][bk][bn + 4], q + 4, true);
    };

    float acc[4][4][4];
#pragma unroll
    for (int i = 0; i < 4; i++)
#pragma unroll
        for (int j = 0; j < 4; j++)
#pragma unroll
            for (int c = 0; c < 4; c++) acc[i][j][c] = 0.f;

    issue(0, 0); CP_COMMIT();
    issue(1, 1); CP_COMMIT();

    const int NT = 32;
    for (int kt = 0; kt < NT; kt++) {
        const int s = kt & 1;
        if (kt + 1 < NT) { CP_WAIT(1); } else { CP_WAIT(0); }
        __syncthreads();
#pragma unroll
        for (int ks = 0; ks < 16; ks += 8) {
            unsigned afr[4][4], bfr[4][2];
#pragma unroll
            for (int mf = 0; mf < 4; mf++) {
                const int m0 = wm * 64 + mf * 16 + gid;
                afr[mf][0] = __float_as_uint(As[s][m0][ks + tig]);
                afr[mf][1] = __float_as_uint(As[s][m0 + 8][ks + tig]);
                afr[mf][2] = __float_as_uint(As[s][m0][ks + tig + 4]);
                afr[mf][3] = __float_as_uint(As[s][m0 + 8][ks + tig + 4]);
            }
#pragma unroll
            for (int nf = 0; nf < 4; nf++) {
                const int n0 = wn * 32 + nf * 8 + gid;
                bfr[nf][0] = __float_as_uint(Bs[s][ks + tig][n0]);
                bfr[nf][1] = __float_as_uint(Bs[s][ks + tig + 4][n0]);
            }
#pragma unroll
            for (int mf = 0; mf < 4; mf++)
#pragma unroll
                for (int nf = 0; nf < 4; nf++)
                    mma_tf32(acc[mf][nf], afr[mf], bfr[nf]);
        }
        __syncthreads();
        if (kt + 2 < NT) { issue(kt + 2, s); CP_COMMIT(); }
    }

#pragma unroll
    for (int mf = 0; mf < 4; mf++) {
        const int row = mBase + wm * 64 + mf * 16 + gid;
#pragma unroll
        for (int nf = 0; nf < 4; nf++) {
            const int col = nBase + wn * 32 + nf * 8 + tig * 2;
            C[(size_t)row * 512 + col]           = acc[mf][nf][0];
            C[(size_t)row * 512 + col + 1]       = acc[mf][nf][1];
            C[(size_t)(row + 8) * 512 + col]     = acc[mf][nf][2];
            C[(size_t)(row + 8) * 512 + col + 1] = acc[mf][nf][3];
        }
    }
}

// ---------------------------------------------------------------------------
// fp32 GEMM (logits): C = [A1|A2] @ W + bias, remapped out layout.
// ---------------------------------------------------------------------------
__global__ __launch_bounds__(256) void gemm_fused(
    const float* __restrict__ A1, const float* __restrict__ A2,
    const float* __restrict__ W, const float* __restrict__ bias,
    float* __restrict__ C, int N, int K)
{
    __shared__ float sA[16][65];
    __shared__ float sB[16][68];
    const int tid = threadIdx.x;
    const int tx = tid & 15, ty = tid >> 4;
    const int mBase = blockIdx.y * 64, nBase = blockIdx.x * 64;

    const int lam = tid >> 2, lak = (tid & 3) * 4;
    const int lbk = tid >> 4, lbn = (tid & 15) * 4;

    float acc[4][4];
#pragma unroll
    for (int i = 0; i < 4; i++)
#pragma unroll
        for (int j = 0; j < 4; j++) acc[i][j] = 0.f;

    for (int k0 = 0; k0 < K; k0 += 16) {
        float av[4], bv[4];
#pragma unroll
        for (int i = 0; i < 4; i++) {
            const int kk = k0 + lak + i;
            av[i] = (kk < 512) ? A1[(size_t)(mBase + lam) * 512 + kk]
                               : A2[(size_t)(mBase + lam) * 512 + kk - 512];
        }
#pragma unroll
        for (int i = 0; i < 4; i++) {
            const int nn = nBase + lbn + i;
            bv[i] = (nn < N) ? W[(size_t)(k0 + lbk) * N + nn] : 0.f;
        }
        __syncthreads();
#pragma unroll
        for (int i = 0; i < 4; i++) sA[lak + i][lam] = av[i];
#pragma unroll
        for (int i = 0; i < 4; i++) sB[lbk][lbn + i] = bv[i];
        __syncthreads();
#pragma unroll
        for (int kk = 0; kk < 16; kk++) {
            float a[4], b[4];
#pragma unroll
            for (int i = 0; i < 4; i++) a[i] = sA[kk][ty * 4 + i];
#pragma unroll
            for (int j = 0; j < 4; j++) b[j] = sB[kk][tx * 4 + j];
#pragma unroll
            for (int i = 0; i < 4; i++)
#pragma unroll
                for (int j = 0; j < 4; j++) acc[i][j] += a[i] * b[j];
        }
    }

#pragma unroll
    for (int i = 0; i < 4; i++) {
        const int row = mBase + ty * 4 + i;
#pragma unroll
        for (int j = 0; j < 4; j++) {
            const int col = nBase + tx * 4 + j;
            if (col < N) {
                const float v = acc[i][j] + bias[col];
                const int t = row >> 7, b = row & 127;
                C[(size_t)(b * TSTEPS + t) * NCLS + col] = v;
            }
        }
    }
}

// ---------------------------------------------------------------------------
// Attention logits: att[t,b,pos] = sum_ch tanh(fproj[b,pos,ch]+hp[t,b,ch])*wa[ch]
// fproj register-resident (read once). grid (8 pos-chunks, 128 b), 256 thr
// ---------------------------------------------------------------------------
__global__ __launch_bounds__(256) void att_kernel(
    const float* __restrict__ fproj, const float* __restrict__ hp,
    const float* __restrict__ wa, float* __restrict__ att)
{
    __shared__ float sHp[8 * 65];
    __shared__ float sWa[8 * 65];
    const int tid = threadIdx.x;
    const int posl = tid >> 3, tch = tid & 7;
    const int b = blockIdx.y, pos0 = blockIdx.x * 32;
    const int ch0 = tch * 64;

    float fr[64];
    const float* fp = fproj + (size_t)(b * NPOS + pos0 + posl) * 512 + ch0;
#pragma unroll
    for (int i = 0; i < 16; i++) {
        const float4 v = *(const float4*)(fp + i * 4);
        fr[i * 4 + 0] = v.x; fr[i * 4 + 1] = v.y;
        fr[i * 4 + 2] = v.z; fr[i * 4 + 3] = v.w;
    }
    for (int k = tid; k < 512; k += 256)
        sWa[(k >> 6) * 65 + (k & 63)] = wa[k];

    for (int t = 0; t < TSTEPS; t++) {
        __syncthreads();
        const float* hrow = hp + (size_t)(t * BB + b) * 512;
        for (int k = tid; k < 512; k += 256)
            sHp[(k >> 6) * 65 + (k & 63)] = hrow[k];
        __syncthreads();
        float s = 0.f;
#pragma unroll
        for (int i = 0; i < 64; i++) {
            const float x = fr[i] + sHp[tch * 65 + i];
            s += fast_tanh(x) * sWa[tch * 65 + i];
        }
        s += __shfl_down_sync(0xffffffffu, s, 4, 8);
        s += __shfl_down_sync(0xffffffffu, s, 2, 8);
        s += __shfl_down_sync(0xffffffffu, s, 1, 8);
        if (tch == 0)
            att[(size_t)(t * BB + b) * NPOS + pos0 + posl] = s;
    }
}

// ---------------------------------------------------------------------------
// Softmax over 256 positions per (t,b). grid 3968, 256 threads
// ---------------------------------------------------------------------------
__global__ __launch_bounds__(256) void softmax_kernel(float* __restrict__ att)
{
    const int row = blockIdx.x, tid = threadIdx.x;
    const int lane = tid & 31, warp = tid >> 5;
    __shared__ float rmax[8], rsum[8];
    const float v = att[(size_t)row * NPOS + tid];
    float m = v;
#pragma unroll
    for (int o = 16; o; o >>= 1) m = fmaxf(m, __shfl_xor_sync(0xffffffffu, m, o));
    if (lane == 0) rmax[warp] = m;
    __syncthreads();
    float M = rmax[0];
#pragma unroll
    for (int i = 1; i < 8; i++) M = fmaxf(M, rmax[i]);
    const float e = __expf(v - M);
    float s = e;
#pragma unroll
    for (int o = 16; o; o >>= 1) s += __shfl_xor_sync(0xffffffffu, s, o);
    if (lane == 0) rsum[warp] = s;
    __syncthreads();
    float S = 0.f;
#pragma unroll
    for (int i = 0; i < 8; i++) S += rsum[i];
    att[(size_t)row * NPOS + tid] = e / S;
}

// ---------------------------------------------------------------------------
// Glimpse: glim[t,b,c] = sum_pos att[t,b,pos] * features[b,pos,c]
// ---------------------------------------------------------------------------
__global__ __launch_bounds__(256) void glimpse_kernel(
    const float* __restrict__ F, const float* __restrict__ att,
    float* __restrict__ glim)
{
    __shared__ float sF[NPOS * 32];
    __shared__ float sA[NPOS];
    __shared__ float sP[8][33];
    const int tid = threadIdx.x;
    const int b = blockIdx.y, ch0 = blockIdx.x * 32;

    for (int idx = tid; idx < NPOS * 32; idx += 256) {
        const int pos = idx >> 5, ch = idx & 31;
        sF[pos * 32 + ch] = F[(size_t)(b * NPOS + pos) * 512 + ch0 + ch];
    }
    const int pg = tid >> 5, ch = tid & 31;

    for (int t = 0; t < TSTEPS; t++) {
        __syncthreads();
        sA[tid] = att[(size_t)(t * BB + b) * NPOS + tid];
        __syncthreads();
        float s = 0.f;
#pragma unroll
        for (int p = 0; p < 32; p++)
            s += sA[pg * 32 + p] * sF[(pg * 32 + p) * 32 + ch];
        sP[pg][ch] = s;
        __syncthreads();
        if (tid < 32) {
            float g = 0.f;
#pragma unroll
            for (int i = 0; i < 8; i++) g += sP[i][tid];
            glim[(size_t)(t * BB + b) * 512 + ch0 + tid] = g;
        }
    }
}

// ---------------------------------------------------------------------------
// Launch
// ---------------------------------------------------------------------------
extern "C" void kernel_launch(void* const* d_in, const int* in_sizes, int n_in,
                              void* d_out, int out_size)
{
    const float* features = (const float*)d_in[0];
    const float* holistic = (const float*)d_in[1];
    const int*   gt       = (const int*)  d_in[2];
    const float* embed_W  = (const float*)d_in[3];
    const float* k0   = (const float*)d_in[4];
    const float* rk0  = (const float*)d_in[5];
    const float* b0   = (const float*)d_in[6];
    const float* k1   = (const float*)d_in[7];
    const float* rk1  = (const float*)d_in[8];
    const float* b1   = (const float*)d_in[9];
    const float* Wh   = (const float*)d_in[10];
    const float* Wf   = (const float*)d_in[11];
    const float* bf   = (const float*)d_in[12];
    const float* wa   = (const float*)d_in[13];
    const float* outW = (const float*)d_in[14];
    const float* outb = (const float*)d_in[15];
    float* out = (float*)d_out;

    float* S = nullptr;
    cudaGetSymbolAddress((void**)&S, g_scratch);

    float* fproj = S + OF_FPROJ;
    float* Ek0   = S + OF_EK0;
    float* st    = S + OF_ST;
    float* h1all = S + OF_H1ALL;
    float* hp    = S + OF_HP;
    float* att   = S + OF_ATT;
    float* glim  = S + OF_GLIM;
    float* k0t   = S + OF_WT;
    float* rk0t  = S + OF_WT + 1048576;
    float* k1t   = S + OF_WT + 2097152;
    float* rk1t  = S + OF_WT + 3145728;

    cudaFuncSetAttribute(fused_conv_chain,
        cudaFuncAttributeMaxDynamicSharedMemorySize, CONV_SMEM);

    // prep (1 launch) + embedding table
    reorder_w4<<<dim3(512, 4), 256>>>(k0, rk0, k1, rk1, k0t);
    ek0_kernel<<<dim3(8, 112), 256>>>(embed_W, k0, Ek0);

    // conv + whole LSTM chain overlapped in ONE launch
    fused_conv_chain<<<64 + 1024, 256, CONV_SMEM>>>(
        features, Wf, bf, fproj,
        Ek0, gt, holistic, k0t, rk0t, k1t, rk1t, b0, b1, st, h1all);

    // batched epilogue over all 31 steps
    gemm_tc<<<dim3(4, 31), 256>>>(h1all, Wh, hp);
    att_kernel<<<dim3(8, 128), 256>>>(fproj, hp, wa, att);
    softmax_kernel<<<TSTEPS * BB, 256>>>(att);
    glimpse_kernel<<<dim3(16, 128), 256>>>(features, att, glim);
    gemm_fused<<<dim3(2, 62), 256>>>(h1all, glim, outW, outb, out, NCLS, 1024);
}

// round 14
// speedup vs baseline: 2.1917x; 1.0390x over previous
#include <cuda_runtime.h>
#include <cuda_fp16.h>
#include <math.h>

// ---------------------------------------------------------------------------
// Problem constants
// ---------------------------------------------------------------------------
#define BB     128
#define TSTEPS 31
#define NCLS   111
#define NPOS   256          // H*W = 8*32
#define CONV_KT 144         // 4608 / 32
#define CHAIN_BLOCKS 64u

// ---------------------------------------------------------------------------
// Scratch: one __device__ global array (no runtime allocation allowed)
// ---------------------------------------------------------------------------
#define OF_FPROJ  0u          // 32768*512       = 16777216
#define OF_EK0    16777216u   // 112*2048        = 229376
#define OF_ST     17006592u   // 8 * 65536       = 524288
#define OF_H1ALL  17530880u   // 31*65536        = 2031616
#define OF_HP     19562496u   // 31*65536        = 2031616
#define OF_ATT    21594112u   // 31*128*256      = 1015808
#define OF_GLIM   22609920u   // 31*65536        = 2031616
#define OF_WT     24641536u   // 4 * 512*2048    = 4194304
#define OF_FH     28835840u   // 16.7M half      = 8388608 floats
#define OF_WTH    37224448u   // 512*4608 half   = 1179648 floats
#define SCRATCH_TOTAL 38404096u
__device__ float g_scratch[SCRATCH_TOTAL];

// grid barrier state (monotone generation; robust across graph replays)
__device__ unsigned g_cnt = 0;
__device__ volatile unsigned g_gen = 0;

// ---------------------------------------------------------------------------
// Helpers
// ---------------------------------------------------------------------------
__device__ __forceinline__ float tf32r(float x) {
    unsigned u; asm("cvt.rna.tf32.f32 %0, %1;" : "=r"(u) : "f"(x));
    return __uint_as_float(u);
}
__device__ __forceinline__ float fast_tanh(float x) {
    float r; asm("tanh.approx.f32 %0, %1;" : "=f"(r) : "f"(x));
    return r;
}
__device__ __forceinline__ void mma_tf32(float* d, const unsigned* a, const unsigned* b) {
    asm volatile(
        "mma.sync.aligned.m16n8k8.row.col.f32.tf32.tf32.f32 "
        "{%0,%1,%2,%3}, {%4,%5,%6,%7}, {%8,%9}, {%0,%1,%2,%3};\n"
        : "+f"(d[0]), "+f"(d[1]), "+f"(d[2]), "+f"(d[3])
        : "r"(a[0]), "r"(a[1]), "r"(a[2]), "r"(a[3]), "r"(b[0]), "r"(b[1]));
}
__device__ __forceinline__ void mma_fp16(float* d, const unsigned* a, const unsigned* b) {
    asm volatile(
        "mma.sync.aligned.m16n8k16.row.col.f32.f16.f16.f32 "
        "{%0,%1,%2,%3}, {%4,%5,%6,%7}, {%8,%9}, {%0,%1,%2,%3};\n"
        : "+f"(d[0]), "+f"(d[1]), "+f"(d[2]), "+f"(d[3])
        : "r"(a[0]), "r"(a[1]), "r"(a[2]), "r"(a[3]), "r"(b[0]), "r"(b[1]));
}
__device__ __forceinline__ void cp16(float* dst, const float* src, bool v) {
    unsigned d = (unsigned)__cvta_generic_to_shared(dst);
    int sz = v ? 16 : 0;
    asm volatile("cp.async.ca.shared.global [%0], [%1], 16, %2;\n"
                 :: "r"(d), "l"(src), "r"(sz));
}
__device__ __forceinline__ void cpA(unsigned dst, const void* src, bool v) {
    int sz = v ? 16 : 0;
    asm volatile("cp.async.ca.shared.global [%0], [%1], 16, %2;\n"
                 :: "r"(dst), "l"(src), "r"(sz));
}
#define CP_COMMIT() asm volatile("cp.async.commit_group;\n" ::: "memory")
#define CP_WAIT(n)  asm volatile("cp.async.wait_group %0;\n" :: "n"(n) : "memory")

__device__ __forceinline__ void grid_sync() {
    __syncthreads();
    if (threadIdx.x == 0) {
        __threadfence();
        const unsigned gen = g_gen;
        if (atomicAdd(&g_cnt, 1u) == CHAIN_BLOCKS - 1u) {
            g_cnt = 0;
            __threadfence();
            g_gen = gen + 1u;
        } else {
            while (g_gen == gen) { __nanosleep(40); }
        }
        __threadfence();
    }
    __syncthreads();
}

// ---------------------------------------------------------------------------
// Ek0[s][n] = sum_k embed_W[s][k] * k0[k][n] ; row 111 = zeros (SOS). fp32.
// ---------------------------------------------------------------------------
__global__ __launch_bounds__(256) void ek0_kernel(
    const float* __restrict__ eW, const float* __restrict__ k0,
    float* __restrict__ Ek0)
{
    const int n = blockIdx.x * 256 + threadIdx.x;
    const int s = blockIdx.y;
    float a0 = 0.f, a1 = 0.f, a2 = 0.f, a3 = 0.f;
    if (s < 111) {
        const float* e = eW + s * 512;
        for (int k = 0; k < 512; k += 4) {
            a0 += e[k + 0] * k0[(size_t)(k + 0) * 2048 + n];
            a1 += e[k + 1] * k0[(size_t)(k + 1) * 2048 + n];
            a2 += e[k + 2] * k0[(size_t)(k + 2) * 2048 + n];
            a3 += e[k + 3] * k0[(size_t)(k + 3) * 2048 + n];
        }
    }
    Ek0[(size_t)s * 2048 + n] = (a0 + a1) + (a2 + a3);
}

// ---------------------------------------------------------------------------
// Reorder 4 LSTM weight matrices (gate-interleaved, tf32-rounded) in 1 launch
// ---------------------------------------------------------------------------
__global__ __launch_bounds__(256) void reorder_w4(
    const float* __restrict__ k0, const float* __restrict__ rk0,
    const float* __restrict__ k1, const float* __restrict__ rk1,
    float* __restrict__ out)
{
    const int k = blockIdx.x, w = blockIdx.y;
    const float* src = (w == 0) ? k0 : (w == 1) ? rk0 : (w == 2) ? k1 : rk1;
    float* dst = out + (size_t)w * 1048576;
    for (int n = threadIdx.x; n < 2048; n += 256) {
        const int g = n & 3, j = n >> 2;
        dst[(size_t)k * 2048 + n] = tf32r(src[(size_t)k * 2048 + g * 512 + j]);
    }
}

// ---------------------------------------------------------------------------
// Prep for fp16 conv: Fh = half(features) elementwise; Wth[n][k] = half(Wf[k][n])
// grid 65536 + 2304 (transpose tiles 32x32), 256 threads
// ---------------------------------------------------------------------------
__global__ __launch_bounds__(256) void prep_half(
    const float* __restrict__ F, const float* __restrict__ Wf,
    __half* __restrict__ Fh, __half* __restrict__ Wth)
{
    const int bid = blockIdx.x;
    const int tid = threadIdx.x;
    if (bid < 65536) {
        const int i = bid * 256 + tid;
        Fh[i] = __float2half(F[i]);
    } else {
        __shared__ float t[32][33];
        const int b2 = bid - 65536;              // 0..2303
        const int kb = (b2 % 144) * 32;
        const int nb = (b2 / 144) * 32;
        const int x = tid & 31, y = tid >> 5;    // 32 x 8
#pragma unroll
        for (int j = 0; j < 4; j++)
            t[y + j * 8][x] = Wf[(size_t)(kb + y + j * 8) * 512 + nb + x];
        __syncthreads();
#pragma unroll
        for (int j = 0; j < 4; j++)
            Wth[(size_t)(nb + y + j * 8) * 4608 + kb + x] = __float2half(t[x][y + j * 8]);
    }
}

// ---------------------------------------------------------------------------
// Conv device body: 3x3 SAME implicit GEMM, fp16 m16n8k16 mma (fp32 accum),
// BK=32, 3-stage cp.async. M=32768, N=512, K=4608 (144 k-tiles of 32).
// Tile 128x128, 256 thr (8 warps 2m x 4n, warp tile 64x32).
// smem (halves): A [3][128][40] then B [3][128][40] -> 61440 bytes total.
// cid in [0,1024): nBase = (cid&3)*128, mBase = (cid>>2)*128.
// ---------------------------------------------------------------------------
#define CONV_SMEM 61440
__device__ void conv_body(
    __half* smh, int cid,
    const __half* __restrict__ Fh, const __half* __restrict__ Wth,
    const float* __restrict__ bf, float* __restrict__ fproj)
{
    const int tid = threadIdx.x;
    const int lane = tid & 31, warp = tid >> 5;
    const int wm = warp >> 2, wn = warp & 3;
    const int gid = lane >> 2, tig = lane & 3;
    const int nBase = (cid & 3) * 128;
    const int mBase = (cid >> 2) * 128;
    const unsigned smem_base = (unsigned)__cvta_generic_to_shared(smh);

    auto issue = [&](int kt, int s) {
        const int r = kt >> 4;                 // kh*3+kw (k-tile never crosses ci)
        const int ci0 = (kt & 15) << 5;
        const int kh = r / 3;
        const int kw = r - kh * 3;
        const unsigned Abase = smem_base + (unsigned)s * 10240u;
        const unsigned Bbase = smem_base + 30720u + (unsigned)s * 10240u;
#pragma unroll
        for (int j = 0; j < 2; j++) {
            const int c = tid * 2 + j;         // 512 chunks each for A and B
            const int row = c >> 2, q = c & 3; // 4 x 16B per 64B row
            // A: pixel row with conv offset
            const int gm = mBase + row;
            const int ab = gm >> 8, ah = (gm >> 5) & 7, aw = gm & 31;
            const int ih = ah + kh - 1, iw = aw + kw - 1;
            const bool v = ((unsigned)ih < 8u) && ((unsigned)iw < 32u);
            const __half* ps = Fh + (((size_t)((ab * 8 + ih) * 32 + iw)) << 9) + ci0 + q * 8;
            cpA(Abase + (unsigned)(row * 80 + q * 16), v ? ps : Fh, v);
            // B: Wth[n][k] row (k-contiguous)
            const __half* qs = Wth + (size_t)(nBase + row) * 4608 + kt * 32 + q * 8;
            cpA(Bbase + (unsigned)(row * 80 + q * 16), qs, true);
        }
    };

    float acc[4][4][4];
#pragma unroll
    for (int i = 0; i < 4; i++)
#pragma unroll
        for (int j = 0; j < 4; j++)
#pragma unroll
            for (int c = 0; c < 4; c++) acc[i][j][c] = 0.f;

    issue(0, 0); CP_COMMIT();
    issue(1, 1); CP_COMMIT();
    issue(2, 2); CP_COMMIT();

    for (int kt = 0; kt < CONV_KT; kt++) {
        const int s = kt % 3;
        if (kt < CONV_KT - 2)       { CP_WAIT(2); }
        else if (kt == CONV_KT - 2) { CP_WAIT(1); }
        else                        { CP_WAIT(0); }
        __syncthreads();

        const __half* A = smh + s * 5120;
        const __half* B = smh + 15360 + s * 5120;
#pragma unroll
        for (int ks = 0; ks < 2; ks++) {       // two k16 sub-tiles of the K32
            unsigned afr[4][4], bfr[4][2];
#pragma unroll
            for (int mf = 0; mf < 4; mf++) {
                const int m0 = wm * 64 + mf * 16 + gid;
                const __half* ap  = A + m0 * 40 + ks * 16;
                const __half* ap8 = ap + 8 * 40;
                afr[mf][0] = *(const unsigned*)(ap  + tig * 2);
                afr[mf][1] = *(const unsigned*)(ap8 + tig * 2);
                afr[mf][2] = *(const unsigned*)(ap  + 8 + tig * 2);
                afr[mf][3] = *(const unsigned*)(ap8 + 8 + tig * 2);
            }
#pragma unroll
            for (int nf = 0; nf < 4; nf++) {
                const int n0 = wn * 32 + nf * 8 + gid;
                const __half* bp = B + n0 * 40 + ks * 16;
                bfr[nf][0] = *(const unsigned*)(bp + tig * 2);
                bfr[nf][1] = *(const unsigned*)(bp + 8 + tig * 2);
            }
#pragma unroll
            for (int mf = 0; mf < 4; mf++)
#pragma unroll
                for (int nf = 0; nf < 4; nf++)
                    mma_fp16(acc[mf][nf], afr[mf], bfr[nf]);
        }
        __syncthreads();
        if (kt + 3 < CONV_KT) { issue(kt + 3, s); CP_COMMIT(); }
    }

#pragma unroll
    for (int mf = 0; mf < 4; mf++) {
        const int row = mBase + wm * 64 + mf * 16 + gid;
#pragma unroll
        for (int nf = 0; nf < 4; nf++) {
            const int col = nBase + wn * 32 + nf * 8 + tig * 2;
            const float bb0 = bf[col], bb1 = bf[col + 1];
            fproj[(size_t)row * 512 + col]           = acc[mf][nf][0] + bb0;
            fproj[(size_t)row * 512 + col + 1]       = acc[mf][nf][1] + bb1;
            fproj[(size_t)(row + 8) * 512 + col]     = acc[mf][nf][2] + bb0;
            fproj[(size_t)(row + 8) * 512 + col + 1] = acc[mf][nf][3] + bb1;
        }
    }
}

// ---------------------------------------------------------------------------
// LSTM cell for the chain: 256 threads, block tile 64m x 64n' (n' = j*4+gate).
// 8 warps (2m x 4n), warp tile 32x16. tf32 path (bit-identical to R9/R12).
// ---------------------------------------------------------------------------
struct ChainSh2 {
    float As[16][68];   // [k][m]
    float Bs[16][72];   // [k][n'] pitch 72 floats
    float Zs[64][68];
};

__device__ void lstm_cell2(
    ChainSh2* sh, int nTile, int mTile,
    const float* __restrict__ Ek0, const int* __restrict__ gt, int tstep,
    const float* __restrict__ X1, const float* __restrict__ W1t,
    const float* __restrict__ X2, const float* __restrict__ W2t,
    const float* __restrict__ bias, const float* __restrict__ c_in,
    float* __restrict__ h_out, float* __restrict__ c_out,
    float* __restrict__ h_out2)
{
    const int tid = threadIdx.x;
    const int lane = tid & 31, warp = tid >> 5;
    const int wm = warp >> 2, wn = warp & 3;
    const int gid = lane >> 2, tig = lane & 3;
    const int nBase = nTile * 64;
    const int mBase = mTile * 64;

    const int am = tid >> 2, ak = (tid & 3) * 4;
    const int bk = tid >> 4, bn = (tid & 15) * 4;

    const int Ktot = X2 ? 1024 : 512;

    float acc[2][2][4];
#pragma unroll
    for (int i = 0; i < 2; i++)
#pragma unroll
        for (int j = 0; j < 2; j++)
#pragma unroll
            for (int c = 0; c < 4; c++) acc[i][j][c] = 0.f;

    float4 aR, bR;
    aR = *(const float4*)(X1 + (size_t)(mBase + am) * 512 + ak);
    bR = *(const float4*)(W1t + (size_t)bk * 2048 + nBase + bn);

    for (int kt = 0; kt < Ktot; kt += 16) {
        __syncthreads();
        sh->As[ak + 0][am] = tf32r(aR.x);
        sh->As[ak + 1][am] = tf32r(aR.y);
        sh->As[ak + 2][am] = tf32r(aR.z);
        sh->As[ak + 3][am] = tf32r(aR.w);
        *(float4*)&sh->Bs[bk][bn] = bR;
        __syncthreads();

        const int kn = kt + 16;
        if (kn < Ktot) {
            const float* X = (kn < 512) ? X1 : X2;
            const float* W = (kn < 512) ? W1t : W2t;
            const int kk = kn & 511;
            aR = *(const float4*)(X + (size_t)(mBase + am) * 512 + kk + ak);
            bR = *(const float4*)(W + (size_t)(kk + bk) * 2048 + nBase + bn);
        }

#pragma unroll
        for (int ks = 0; ks < 16; ks += 8) {
            unsigned af[2][4], bf2[2][2];
#pragma unroll
            for (int mf = 0; mf < 2; mf++) {
                const int m0 = wm * 32 + mf * 16 + gid;
                af[mf][0] = __float_as_uint(sh->As[ks + tig][m0]);
                af[mf][1] = __float_as_uint(sh->As[ks + tig][m0 + 8]);
                af[mf][2] = __float_as_uint(sh->As[ks + tig + 4][m0]);
                af[mf][3] = __float_as_uint(sh->As[ks + tig + 4][m0 + 8]);
            }
#pragma unroll
            for (int nf = 0; nf < 2; nf++) {
                const int n0 = wn * 16 + nf * 8 + gid;
                bf2[nf][0] = __float_as_uint(sh->Bs[ks + tig][n0]);
                bf2[nf][1] = __float_as_uint(sh->Bs[ks + tig + 4][n0]);
            }
#pragma unroll
            for (int mf = 0; mf < 2; mf++)
#pragma unroll
                for (int nf = 0; nf < 2; nf++)
                    mma_tf32(acc[mf][nf], af[mf], bf2[nf]);
        }
    }

    __syncthreads();
#pragma unroll
    for (int mf = 0; mf < 2; mf++) {
        const int row = wm * 32 + mf * 16 + gid;
#pragma unroll
        for (int nf = 0; nf < 2; nf++) {
            const int col = wn * 16 + nf * 8 + tig * 2;
            sh->Zs[row][col]         = acc[mf][nf][0];
            sh->Zs[row][col + 1]     = acc[mf][nf][1];
            sh->Zs[row + 8][col]     = acc[mf][nf][2];
            sh->Zs[row + 8][col + 1] = acc[mf][nf][3];
        }
    }
    __syncthreads();

    const int r  = tid >> 2;
    const int j0 = (tid & 3) * 4;
    const int gr = mBase + r;
    int sym = 0;
    if (Ek0) sym = (tstep == 0) ? 111 : gt[gr * TSTEPS + tstep - 1];

#pragma unroll
    for (int jj = 0; jj < 4; jj++) {
        const int j  = j0 + jj;
        const int jg = nTile * 16 + j;
        float zi = sh->Zs[r][j * 4 + 0] + bias[jg];
        float zf = sh->Zs[r][j * 4 + 1] + bias[512 + jg];
        float zg = sh->Zs[r][j * 4 + 2] + bias[1024 + jg];
        float zo = sh->Zs[r][j * 4 + 3] + bias[1536 + jg];
        if (Ek0) {
            const float* e = Ek0 + (size_t)sym * 2048;
            zi += e[jg]; zf += e[512 + jg]; zg += e[1024 + jg]; zo += e[1536 + jg];
        }
        const float ci = c_in ? c_in[(size_t)gr * 512 + jg] : 0.f;
        const float si = 1.f / (1.f + expf(-zi));
        const float sf = 1.f / (1.f + expf(-zf));
        const float so = 1.f / (1.f + expf(-zo));
        const float c2 = sf * ci + si * tanhf(zg);
        const float h2 = so * tanhf(c2);
        h_out[(size_t)gr * 512 + jg] = h2;
        c_out[(size_t)gr * 512 + jg] = c2;
        if (h_out2) h_out2[(size_t)gr * 512 + jg] = h2;
    }
}

__device__ void chain_body(
    ChainSh2* sh, int cbid,
    const float* __restrict__ Ek0, const int* __restrict__ gt,
    const float* __restrict__ hol,
    const float* __restrict__ k0t, const float* __restrict__ rk0t,
    const float* __restrict__ k1t, const float* __restrict__ rk1t,
    const float* __restrict__ b0, const float* __restrict__ b1,
    float* __restrict__ st, float* __restrict__ h1all)
{
    const int nTile = cbid & 31;
    const int mTile = cbid >> 5;
    float* h0b[2] = { st,          st + 65536 };
    float* c0b[2] = { st + 131072, st + 196608 };
    float* h1b[2] = { st + 262144, st + 327680 };
    float* c1b[2] = { st + 393216, st + 458752 };

    lstm_cell2(sh, nTile, mTile, nullptr, nullptr, 0, hol, k0t, nullptr, nullptr,
               b0, nullptr, h0b[0], c0b[0], nullptr);
    grid_sync();
    lstm_cell2(sh, nTile, mTile, nullptr, nullptr, 0, h0b[0], k1t, nullptr, nullptr,
               b1, nullptr, h1b[0], c1b[0], nullptr);
    grid_sync();

    for (int t = 0; t < TSTEPS; t++) {
        const int p = t & 1, q = p ^ 1;
        lstm_cell2(sh, nTile, mTile, Ek0, gt, t, h0b[p], rk0t, nullptr, nullptr,
                   b0, c0b[p], h0b[q], c0b[q], nullptr);
        grid_sync();
        lstm_cell2(sh, nTile, mTile, nullptr, nullptr, 0, h0b[q], k1t, h1b[p], rk1t,
                   b1, c1b[p], h1b[q], c1b[q],
                   h1all + (size_t)t * BB * 512);
        if (t + 1 < TSTEPS) grid_sync();
    }
}

// ---------------------------------------------------------------------------
// Fused kernel: bids 0..63 = persistent LSTM chain (wave-1 resident -> grid
// barrier safe); bids 64..1087 = fp16 conv. Overlap on the chip.
// ---------------------------------------------------------------------------
__global__ __launch_bounds__(256, 2) void fused_conv_chain(
    const __half* __restrict__ Fh, const __half* __restrict__ Wth,
    const float* __restrict__ bf, float* __restrict__ fproj,
    const float* __restrict__ Ek0, const int* __restrict__ gt,
    const float* __restrict__ hol,
    const float* __restrict__ k0t, const float* __restrict__ rk0t,
    const float* __restrict__ k1t, const float* __restrict__ rk1t,
    const float* __restrict__ b0, const float* __restrict__ b1,
    float* __restrict__ st, float* __restrict__ h1all)
{
    extern __shared__ float smx[];
    if (blockIdx.x < (int)CHAIN_BLOCKS) {
        chain_body((ChainSh2*)smx, blockIdx.x, Ek0, gt, hol,
                   k0t, rk0t, k1t, rk1t, b0, b1, st, h1all);
    } else {
        conv_body((__half*)smx, blockIdx.x - (int)CHAIN_BLOCKS, Fh, Wth, bf, fproj);
    }
}

// ---------------------------------------------------------------------------
// tf32 mma GEMM for hp = h1all @ Wh.  M=3968, N=512, K=512.
// ---------------------------------------------------------------------------
__global__ __launch_bounds__(256) void gemm_tc(
    const float* __restrict__ A, const float* __restrict__ W,
    float* __restrict__ C)
{
    __shared__ float As[2][128][20];
    __shared__ float Bs[2][16][132];

    const int tid = threadIdx.x;
    const int lane = tid & 31, warp = tid >> 5;
    const int wm = warp >> 2, wn = warp & 3;
    const int gid = lane >> 2, tig = lane & 3;
    const int mBase = blockIdx.y * 128, nBase = blockIdx.x * 128;

    const int am = tid >> 1;
    const int ak = (tid & 1) * 8;
    const int bk = tid >> 4;
    const int bn = (tid & 15) * 8;

    auto issue = [&](int kt, int s) {
        const float* p = A + (size_t)(mBase + am) * 512 + kt * 16 + ak;
        cp16(&As[s][am][ak],     p,     true);
        cp16(&As[s][am][ak + 4], p + 4, true);
        const float* q = W + (size_t)(kt * 16 + bk) * 512 + nBase + bn;
        cp16(&Bs[s][bk][bn],     q,     true);
        cp16(&Bs[s][bk][bn + 4], q + 4, true);
    };

    float acc[4][4][4];
#pragma unroll
    for (int i = 0; i < 4; i++)
#pragma unroll
        for (int j = 0; j < 4; j++)
#pragma unroll
            for (int c = 0; c < 4; c++) acc[i][j][c] = 0.f;

    issue(0, 0); CP_COMMIT();
    issue(1, 1); CP_COMMIT();

    const int NT = 32;
    for (int kt = 0; kt < NT; kt++) {
        const int s = kt & 1;
        if (kt + 1 < NT) { CP_WAIT(1); } else { CP_WAIT(0); }
        __syncthreads();
#pragma unroll
        for (int ks = 0; ks < 16; ks += 8) {
            unsigned afr[4][4], bfr[4][2];
#pragma unroll
            for (int mf = 0; mf < 4; mf++) {
                const int m0 = wm * 64 + mf * 16 + gid;
                afr[mf][0] = __float_as_uint(As[s][m0][ks + tig]);
                afr[mf][1] = __float_as_uint(As[s][m0 + 8][ks + tig]);
                afr[mf][2] = __float_as_uint(As[s][m0][ks + tig + 4]);
                afr[mf][3] = __float_as_uint(As[s][m0 + 8][ks + tig + 4]);
            }
#pragma unroll
            for (int nf = 0; nf < 4; nf++) {
                const int n0 = wn * 32 + nf * 8 + gid;
                bfr[nf][0] = __float_as_uint(Bs[s][ks + tig][n0]);
                bfr[nf][1] = __float_as_uint(Bs[s][ks + tig + 4][n0]);
            }
#pragma unroll
            for (int mf = 0; mf < 4; mf++)
#pragma unroll
                for (int nf = 0; nf < 4; nf++)
                    mma_tf32(acc[mf][nf], afr[mf], bfr[nf]);
        }
        __syncthreads();
        if (kt + 2 < NT) { issue(kt + 2, s); CP_COMMIT(); }
    }

#pragma unroll
    for (int mf = 0; mf < 4; mf++) {
        const int row = mBase + wm * 64 + mf * 16 + gid;
#pragma unroll
        for (int nf = 0; nf < 4; nf++) {
            const int col = nBase + wn * 32 + nf * 8 + tig * 2;
            C[(size_t)row * 512 + col]           = acc[mf][nf][0];
            C[(size_t)row * 512 + col + 1]       = acc[mf][nf][1];
            C[(size_t)(row + 8) * 512 + col]     = acc[mf][nf][2];
            C[(size_t)(row + 8) * 512 + col + 1] = acc[mf][nf][3];
        }
    }
}

// ---------------------------------------------------------------------------
// fp32 GEMM (logits): C = [A1|A2] @ W + bias, remapped out layout.
// ---------------------------------------------------------------------------
__global__ __launch_bounds__(256) void gemm_fused(
    const float* __restrict__ A1, const float* __restrict__ A2,
    const float* __restrict__ W, const float* __restrict__ bias,
    float* __restrict__ C, int N, int K)
{
    __shared__ float sA[16][65];
    __shared__ float sB[16][68];
    const int tid = threadIdx.x;
    const int tx = tid & 15, ty = tid >> 4;
    const int mBase = blockIdx.y * 64, nBase = blockIdx.x * 64;

    const int lam = tid >> 2, lak = (tid & 3) * 4;
    const int lbk = tid >> 4, lbn = (tid & 15) * 4;

    float acc[4][4];
#pragma unroll
    for (int i = 0; i < 4; i++)
#pragma unroll
        for (int j = 0; j < 4; j++) acc[i][j] = 0.f;

    for (int k0 = 0; k0 < K; k0 += 16) {
        float av[4], bv[4];
#pragma unroll
        for (int i = 0; i < 4; i++) {
            const int kk = k0 + lak + i;
            av[i] = (kk < 512) ? A1[(size_t)(mBase + lam) * 512 + kk]
                               : A2[(size_t)(mBase + lam) * 512 + kk - 512];
        }
#pragma unroll
        for (int i = 0; i < 4; i++) {
            const int nn = nBase + lbn + i;
            bv[i] = (nn < N) ? W[(size_t)(k0 + lbk) * N + nn] : 0.f;
        }
        __syncthreads();
#pragma unroll
        for (int i = 0; i < 4; i++) sA[lak + i][lam] = av[i];
#pragma unroll
        for (int i = 0; i < 4; i++) sB[lbk][lbn + i] = bv[i];
        __syncthreads();
#pragma unroll
        for (int kk = 0; kk < 16; kk++) {
            float a[4], b[4];
#pragma unroll
            for (int i = 0; i < 4; i++) a[i] = sA[kk][ty * 4 + i];
#pragma unroll
            for (int j = 0; j < 4; j++) b[j] = sB[kk][tx * 4 + j];
#pragma unroll
            for (int i = 0; i < 4; i++)
#pragma unroll
                for (int j = 0; j < 4; j++) acc[i][j] += a[i] * b[j];
        }
    }

#pragma unroll
    for (int i = 0; i < 4; i++) {
        const int row = mBase + ty * 4 + i;
#pragma unroll
        for (int j = 0; j < 4; j++) {
            const int col = nBase + tx * 4 + j;
            if (col < N) {
                const float v = acc[i][j] + bias[col];
                const int t = row >> 7, b = row & 127;
                C[(size_t)(b * TSTEPS + t) * NCLS + col] = v;
            }
        }
    }
}

// ---------------------------------------------------------------------------
// Attention logits: att[t,b,pos] = sum_ch tanh(fproj[b,pos,ch]+hp[t,b,ch])*wa[ch]
// fproj register-resident (read once). grid (8 pos-chunks, 128 b), 256 thr
// ---------------------------------------------------------------------------
__global__ __launch_bounds__(256) void att_kernel(
    const float* __restrict__ fproj, const float* __restrict__ hp,
    const float* __restrict__ wa, float* __restrict__ att)
{
    __shared__ float sHp[8 * 65];
    __shared__ float sWa[8 * 65];
    const int tid = threadIdx.x;
    const int posl = tid >> 3, tch = tid & 7;
    const int b = blockIdx.y, pos0 = blockIdx.x * 32;
    const int ch0 = tch * 64;

    float fr[64];
    const float* fp = fproj + (size_t)(b * NPOS + pos0 + posl) * 512 + ch0;
#pragma unroll
    for (int i = 0; i < 16; i++) {
        const float4 v = *(const float4*)(fp + i * 4);
        fr[i * 4 + 0] = v.x; fr[i * 4 + 1] = v.y;
        fr[i * 4 + 2] = v.z; fr[i * 4 + 3] = v.w;
    }
    for (int k = tid; k < 512; k += 256)
        sWa[(k >> 6) * 65 + (k & 63)] = wa[k];

    for (int t = 0; t < TSTEPS; t++) {
        __syncthreads();
        const float* hrow = hp + (size_t)(t * BB + b) * 512;
        for (int k = tid; k < 512; k += 256)
            sHp[(k >> 6) * 65 + (k & 63)] = hrow[k];
        __syncthreads();
        float s = 0.f;
#pragma unroll
        for (int i = 0; i < 64; i++) {
            const float x = fr[i] + sHp[tch * 65 + i];
            s += fast_tanh(x) * sWa[tch * 65 + i];
        }
        s += __shfl_down_sync(0xffffffffu, s, 4, 8);
        s += __shfl_down_sync(0xffffffffu, s, 2, 8);
        s += __shfl_down_sync(0xffffffffu, s, 1, 8);
        if (tch == 0)
            att[(size_t)(t * BB + b) * NPOS + pos0 + posl] = s;
    }
}

// ---------------------------------------------------------------------------
// Softmax over 256 positions per (t,b). grid 3968, 256 threads
// ---------------------------------------------------------------------------
__global__ __launch_bounds__(256) void softmax_kernel(float* __restrict__ att)
{
    const int row = blockIdx.x, tid = threadIdx.x;
    const int lane = tid & 31, warp = tid >> 5;
    __shared__ float rmax[8], rsum[8];
    const float v = att[(size_t)row * NPOS + tid];
    float m = v;
#pragma unroll
    for (int o = 16; o; o >>= 1) m = fmaxf(m, __shfl_xor_sync(0xffffffffu, m, o));
    if (lane == 0) rmax[warp] = m;
    __syncthreads();
    float M = rmax[0];
#pragma unroll
    for (int i = 1; i < 8; i++) M = fmaxf(M, rmax[i]);
    const float e = __expf(v - M);
    float s = e;
#pragma unroll
    for (int o = 16; o; o >>= 1) s += __shfl_xor_sync(0xffffffffu, s, o);
    if (lane == 0) rsum[warp] = s;
    __syncthreads();
    float S = 0.f;
#pragma unroll
    for (int i = 0; i < 8; i++) S += rsum[i];
    att[(size_t)row * NPOS + tid] = e / S;
}

// ---------------------------------------------------------------------------
// Glimpse: glim[t,b,c] = sum_pos att[t,b,pos] * features[b,pos,c]
// ---------------------------------------------------------------------------
__global__ __launch_bounds__(256) void glimpse_kernel(
    const float* __restrict__ F, const float* __restrict__ att,
    float* __restrict__ glim)
{
    __shared__ float sF[NPOS * 32];
    __shared__ float sA[NPOS];
    __shared__ float sP[8][33];
    const int tid = threadIdx.x;
    const int b = blockIdx.y, ch0 = blockIdx.x * 32;

    for (int idx = tid; idx < NPOS * 32; idx += 256) {
        const int pos = idx >> 5, ch = idx & 31;
        sF[pos * 32 + ch] = F[(size_t)(b * NPOS + pos) * 512 + ch0 + ch];
    }
    const int pg = tid >> 5, ch = tid & 31;

    for (int t = 0; t < TSTEPS; t++) {
        __syncthreads();
        sA[tid] = att[(size_t)(t * BB + b) * NPOS + tid];
        __syncthreads();
        float s = 0.f;
#pragma unroll
        for (int p = 0; p < 32; p++)
            s += sA[pg * 32 + p] * sF[(pg * 32 + p) * 32 + ch];
        sP[pg][ch] = s;
        __syncthreads();
        if (tid < 32) {
            float g = 0.f;
#pragma unroll
            for (int i = 0; i < 8; i++) g += sP[i][tid];
            glim[(size_t)(t * BB + b) * 512 + ch0 + tid] = g;
        }
    }
}

// ---------------------------------------------------------------------------
// Launch
// ---------------------------------------------------------------------------
extern "C" void kernel_launch(void* const* d_in, const int* in_sizes, int n_in,
                              void* d_out, int out_size)
{
    const float* features = (const float*)d_in[0];
    const float* holistic = (const float*)d_in[1];
    const int*   gt       = (const int*)  d_in[2];
    const float* embed_W  = (const float*)d_in[3];
    const float* k0   = (const float*)d_in[4];
    const float* rk0  = (const float*)d_in[5];
    const float* b0   = (const float*)d_in[6];
    const float* k1   = (const float*)d_in[7];
    const float* rk1  = (const float*)d_in[8];
    const float* b1   = (const float*)d_in[9];
    const float* Wh   = (const float*)d_in[10];
    const float* Wf   = (const float*)d_in[11];
    const float* bf   = (const float*)d_in[12];
    const float* wa   = (const float*)d_in[13];
    const float* outW = (const float*)d_in[14];
    const float* outb = (const float*)d_in[15];
    float* out = (float*)d_out;

    float* S = nullptr;
    cudaGetSymbolAddress((void**)&S, g_scratch);

    float* fproj = S + OF_FPROJ;
    float* Ek0   = S + OF_EK0;
    float* st    = S + OF_ST;
    float* h1all = S + OF_H1ALL;
    float* hp    = S + OF_HP;
    float* att   = S + OF_ATT;
    float* glim  = S + OF_GLIM;
    float* k0t   = S + OF_WT;
    float* rk0t  = S + OF_WT + 1048576;
    float* k1t   = S + OF_WT + 2097152;
    float* rk1t  = S + OF_WT + 3145728;
    __half* Fh  = (__half*)(S + OF_FH);
    __half* Wth = (__half*)(S + OF_WTH);

    cudaFuncSetAttribute(fused_conv_chain,
        cudaFuncAttributeMaxDynamicSharedMemorySize, CONV_SMEM);

    // prep: fp16 conversions, gate-interleaved LSTM weights, embedding table
    prep_half<<<65536 + 2304, 256>>>(features, Wf, Fh, Wth);
    reorder_w4<<<dim3(512, 4), 256>>>(k0, rk0, k1, rk1, k0t);
    ek0_kernel<<<dim3(8, 112), 256>>>(embed_W, k0, Ek0);

    // fp16 conv + whole LSTM chain overlapped in ONE launch
    fused_conv_chain<<<64 + 1024, 256, CONV_SMEM>>>(
        Fh, Wth, bf, fproj,
        Ek0, gt, holistic, k0t, rk0t, k1t, rk1t, b0, b1, st, h1all);

    // batched epilogue over all 31 steps
    gemm_tc<<<dim3(4, 31), 256>>>(h1all, Wh, hp);
    att_kernel<<<dim3(8, 128), 256>>>(fproj, hp, wa, att);
    softmax_kernel<<<TSTEPS * BB, 256>>>(att);
    glimpse_kernel<<<dim3(16, 128), 256>>>(features, att, glim);
    gemm_fused<<<dim3(2, 62), 256>>>(h1all, glim, outW, outb, out, NCLS, 1024);
}

// round 16
// speedup vs baseline: 3.1267x; 1.4266x over previous
#include <cuda_runtime.h>
#include <cuda_fp16.h>
#include <math.h>

// ---------------------------------------------------------------------------
// Problem constants
// ---------------------------------------------------------------------------
#define BB     128
#define TSTEPS 31
#define NCLS   111
#define NPOS   256          // H*W = 8*32
#define CONV_KT 144         // 4608 / 32
#define CHAIN_BLOCKS 128u   // 64 blocks per LSTM lane (cell0 / cell1)

// ---------------------------------------------------------------------------
// Scratch: one __device__ global array (no runtime allocation allowed)
// ---------------------------------------------------------------------------
#define OF_FPROJ  0u          // 32768*512       = 16777216
#define OF_EK0    16777216u   // 112*2048        = 229376
#define OF_ST     17006592u   // 8 * 65536       = 524288
#define OF_H1ALL  17530880u   // 31*65536        = 2031616
#define OF_HP     19562496u   // 31*65536        = 2031616
#define OF_ATT    21594112u   // 31*128*256      = 1015808
#define OF_GLIM   22609920u   // 31*65536        = 2031616
#define OF_WT     24641536u   // 4 * 2048*512 half = 2097152 floats used
#define OF_FH     28835840u   // 16.7M half      = 8388608 floats
#define OF_WTH    37224448u   // 512*4608 half   = 1179648 floats
#define SCRATCH_TOTAL 38404096u
__device__ float g_scratch[SCRATCH_TOTAL];

// grid barrier state (monotone generation; robust across graph replays)
__device__ unsigned g_cnt = 0;
__device__ volatile unsigned g_gen = 0;

// ---------------------------------------------------------------------------
// Helpers
// ---------------------------------------------------------------------------
__device__ __forceinline__ float fast_tanh(float x) {
    float r; asm("tanh.approx.f32 %0, %1;" : "=f"(r) : "f"(x));
    return r;
}
__device__ __forceinline__ void mma_tf32(float* d, const unsigned* a, const unsigned* b) {
    asm volatile(
        "mma.sync.aligned.m16n8k8.row.col.f32.tf32.tf32.f32 "
        "{%0,%1,%2,%3}, {%4,%5,%6,%7}, {%8,%9}, {%0,%1,%2,%3};\n"
        : "+f"(d[0]), "+f"(d[1]), "+f"(d[2]), "+f"(d[3])
        : "r"(a[0]), "r"(a[1]), "r"(a[2]), "r"(a[3]), "r"(b[0]), "r"(b[1]));
}
__device__ __forceinline__ void mma_fp16(float* d, const unsigned* a, const unsigned* b) {
    asm volatile(
        "mma.sync.aligned.m16n8k16.row.col.f32.f16.f16.f32 "
        "{%0,%1,%2,%3}, {%4,%5,%6,%7}, {%8,%9}, {%0,%1,%2,%3};\n"
        : "+f"(d[0]), "+f"(d[1]), "+f"(d[2]), "+f"(d[3])
        : "r"(a[0]), "r"(a[1]), "r"(a[2]), "r"(a[3]), "r"(b[0]), "r"(b[1]));
}
__device__ __forceinline__ void cp16(float* dst, const float* src, bool v) {
    unsigned d = (unsigned)__cvta_generic_to_shared(dst);
    int sz = v ? 16 : 0;
    asm volatile("cp.async.ca.shared.global [%0], [%1], 16, %2;\n"
                 :: "r"(d), "l"(src), "r"(sz));
}
__device__ __forceinline__ void cpA(unsigned dst, const void* src, bool v) {
    int sz = v ? 16 : 0;
    asm volatile("cp.async.ca.shared.global [%0], [%1], 16, %2;\n"
                 :: "r"(dst), "l"(src), "r"(sz));
}
#define CP_COMMIT() asm volatile("cp.async.commit_group;\n" ::: "memory")
#define CP_WAIT(n)  asm volatile("cp.async.wait_group %0;\n" :: "n"(n) : "memory")

__device__ __forceinline__ void grid_sync() {
    __syncthreads();
    if (threadIdx.x == 0) {
        __threadfence();
        const unsigned gen = g_gen;
        if (atomicAdd(&g_cnt, 1u) == CHAIN_BLOCKS - 1u) {
            g_cnt = 0;
            __threadfence();
            g_gen = gen + 1u;
        } else {
            while (g_gen == gen) { __nanosleep(32); }
        }
        __threadfence();
    }
    __syncthreads();
}

// ---------------------------------------------------------------------------
// Ek0[s][n] = sum_k embed_W[s][k] * k0[k][n] ; row 111 = zeros (SOS). fp32.
// ---------------------------------------------------------------------------
__global__ __launch_bounds__(256) void ek0_kernel(
    const float* __restrict__ eW, const float* __restrict__ k0,
    float* __restrict__ Ek0)
{
    const int n = blockIdx.x * 256 + threadIdx.x;
    const int s = blockIdx.y;
    float a0 = 0.f, a1 = 0.f, a2 = 0.f, a3 = 0.f;
    if (s < 111) {
        const float* e = eW + s * 512;
        for (int k = 0; k < 512; k += 4) {
            a0 += e[k + 0] * k0[(size_t)(k + 0) * 2048 + n];
            a1 += e[k + 1] * k0[(size_t)(k + 1) * 2048 + n];
            a2 += e[k + 2] * k0[(size_t)(k + 2) * 2048 + n];
            a3 += e[k + 3] * k0[(size_t)(k + 3) * 2048 + n];
        }
    }
    Ek0[(size_t)s * 2048 + n] = (a0 + a1) + (a2 + a3);
}

// ---------------------------------------------------------------------------
// Reorder 4 LSTM weight matrices to fp16, gate-interleaved AND transposed:
//   Wt'[w][n'][k] = half(src[k][g*512+j]), n' = j*4+g.  grid (2048, 4).
// ---------------------------------------------------------------------------
__global__ __launch_bounds__(256) void reorder_w4h(
    const float* __restrict__ k0, const float* __restrict__ rk0,
    const float* __restrict__ k1, const float* __restrict__ rk1,
    __half* __restrict__ out)
{
    const int np = blockIdx.x;           // n' 0..2047
    const int w = blockIdx.y;
    const float* src = (w == 0) ? k0 : (w == 1) ? rk0 : (w == 2) ? k1 : rk1;
    __half* dst = out + (size_t)w * 1048576 + (size_t)np * 512;
    const int g = np & 3, j = np >> 2;
    for (int k = threadIdx.x; k < 512; k += 256)
        dst[k] = __float2half(src[(size_t)k * 2048 + g * 512 + j]);
}

// ---------------------------------------------------------------------------
// Prep for fp16 conv: Fh = half(features) elementwise; Wth[n][k] = half(Wf[k][n])
// grid 65536 + 2304 (transpose tiles 32x32), 256 threads
// ---------------------------------------------------------------------------
__global__ __launch_bounds__(256) void prep_half(
    const float* __restrict__ F, const float* __restrict__ Wf,
    __half* __restrict__ Fh, __half* __restrict__ Wth)
{
    const int bid = blockIdx.x;
    const int tid = threadIdx.x;
    if (bid < 65536) {
        const int i = bid * 256 + tid;
        Fh[i] = __float2half(F[i]);
    } else {
        __shared__ float t[32][33];
        const int b2 = bid - 65536;              // 0..2303
        const int kb = (b2 % 144) * 32;
        const int nb = (b2 / 144) * 32;
        const int x = tid & 31, y = tid >> 5;    // 32 x 8
#pragma unroll
        for (int j = 0; j < 4; j++)
            t[y + j * 8][x] = Wf[(size_t)(kb + y + j * 8) * 512 + nb + x];
        __syncthreads();
#pragma unroll
        for (int j = 0; j < 4; j++)
            Wth[(size_t)(nb + y + j * 8) * 4608 + kb + x] = __float2half(t[x][y + j * 8]);
    }
}

// ---------------------------------------------------------------------------
// Conv device body (unchanged from R14): fp16 m16n8k16, BK=32, 3-stage
// cp.async. Tile 128x128, 256 thr. cid in [0,1024).
// ---------------------------------------------------------------------------
#define CONV_SMEM 61440
__device__ void conv_body(
    __half* smh, int cid,
    const __half* __restrict__ Fh, const __half* __restrict__ Wth,
    const float* __restrict__ bf, float* __restrict__ fproj)
{
    const int tid = threadIdx.x;
    const int lane = tid & 31, warp = tid >> 5;
    const int wm = warp >> 2, wn = warp & 3;
    const int gid = lane >> 2, tig = lane & 3;
    const int nBase = (cid & 3) * 128;
    const int mBase = (cid >> 2) * 128;
    const unsigned smem_base = (unsigned)__cvta_generic_to_shared(smh);

    auto issue = [&](int kt, int s) {
        const int r = kt >> 4;                 // kh*3+kw (k-tile never crosses ci)
        const int ci0 = (kt & 15) << 5;
        const int kh = r / 3;
        const int kw = r - kh * 3;
        const unsigned Abase = smem_base + (unsigned)s * 10240u;
        const unsigned Bbase = smem_base + 30720u + (unsigned)s * 10240u;
#pragma unroll
        for (int j = 0; j < 2; j++) {
            const int c = tid * 2 + j;         // 512 chunks each for A and B
            const int row = c >> 2, q = c & 3; // 4 x 16B per 64B row
            const int gm = mBase + row;
            const int ab = gm >> 8, ah = (gm >> 5) & 7, aw = gm & 31;
            const int ih = ah + kh - 1, iw = aw + kw - 1;
            const bool v = ((unsigned)ih < 8u) && ((unsigned)iw < 32u);
            const __half* ps = Fh + (((size_t)((ab * 8 + ih) * 32 + iw)) << 9) + ci0 + q * 8;
            cpA(Abase + (unsigned)(row * 80 + q * 16), v ? ps : Fh, v);
            const __half* qs = Wth + (size_t)(nBase + row) * 4608 + kt * 32 + q * 8;
            cpA(Bbase + (unsigned)(row * 80 + q * 16), qs, true);
        }
    };

    float acc[4][4][4];
#pragma unroll
    for (int i = 0; i < 4; i++)
#pragma unroll
        for (int j = 0; j < 4; j++)
#pragma unroll
            for (int c = 0; c < 4; c++) acc[i][j][c] = 0.f;

    issue(0, 0); CP_COMMIT();
    issue(1, 1); CP_COMMIT();
    issue(2, 2); CP_COMMIT();

    for (int kt = 0; kt < CONV_KT; kt++) {
        const int s = kt % 3;
        if (kt < CONV_KT - 2)       { CP_WAIT(2); }
        else if (kt == CONV_KT - 2) { CP_WAIT(1); }
        else                        { CP_WAIT(0); }
        __syncthreads();

        const __half* A = smh + s * 5120;
        const __half* B = smh + 15360 + s * 5120;
#pragma unroll
        for (int ks = 0; ks < 2; ks++) {
            unsigned afr[4][4], bfr[4][2];
#pragma unroll
            for (int mf = 0; mf < 4; mf++) {
                const int m0 = wm * 64 + mf * 16 + gid;
                const __half* ap  = A + m0 * 40 + ks * 16;
                const __half* ap8 = ap + 8 * 40;
                afr[mf][0] = *(const unsigned*)(ap  + tig * 2);
                afr[mf][1] = *(const unsigned*)(ap8 + tig * 2);
                afr[mf][2] = *(const unsigned*)(ap  + 8 + tig * 2);
                afr[mf][3] = *(const unsigned*)(ap8 + 8 + tig * 2);
            }
#pragma unroll
            for (int nf = 0; nf < 4; nf++) {
                const int n0 = wn * 32 + nf * 8 + gid;
                const __half* bp = B + n0 * 40 + ks * 16;
                bfr[nf][0] = *(const unsigned*)(bp + tig * 2);
                bfr[nf][1] = *(const unsigned*)(bp + 8 + tig * 2);
            }
#pragma unroll
            for (int mf = 0; mf < 4; mf++)
#pragma unroll
                for (int nf = 0; nf < 4; nf++)
                    mma_fp16(acc[mf][nf], afr[mf], bfr[nf]);
        }
        __syncthreads();
        if (kt + 3 < CONV_KT) { issue(kt + 3, s); CP_COMMIT(); }
    }

#pragma unroll
    for (int mf = 0; mf < 4; mf++) {
        const int row = mBase + wm * 64 + mf * 16 + gid;
#pragma unroll
        for (int nf = 0; nf < 4; nf++) {
            const int col = nBase + wn * 32 + nf * 8 + tig * 2;
            const float bb0 = bf[col], bb1 = bf[col + 1];
            fproj[(size_t)row * 512 + col]           = acc[mf][nf][0] + bb0;
            fproj[(size_t)row * 512 + col + 1]       = acc[mf][nf][1] + bb1;
            fproj[(size_t)(row + 8) * 512 + col]     = acc[mf][nf][2] + bb0;
            fproj[(size_t)(row + 8) * 512 + col + 1] = acc[mf][nf][3] + bb1;
        }
    }
}

// ---------------------------------------------------------------------------
// fp16 LSTM cell: Z[64m x 64n'] over K (512 or 1024), BK=32, m16n8k16.
// X fp32 -> half in the STS; W pre-converted fp16 Wt'[n'][k]. Fused gating.
// 256 threads, 8 warps (2m x 4n), warp tile 32x16.
// ---------------------------------------------------------------------------
struct ChainShH {
    __half As[64][40];   // [m][k], pitch 40 halves
    __half Bs[64][40];   // [n'][k]
    float  Zs[64][68];
};

__device__ void lstm_cellh(
    ChainShH* sh, int nTile, int mTile,
    const float* __restrict__ Ek0, const int* __restrict__ gt, int tstep,
    const float* __restrict__ X1, const __half* __restrict__ W1t,
    const float* __restrict__ X2, const __half* __restrict__ W2t,
    const float* __restrict__ bias, const float* __restrict__ c_in,
    float* __restrict__ h_out, float* __restrict__ c_out,
    float* __restrict__ h_out2)
{
    const int tid = threadIdx.x;
    const int lane = tid & 31, warp = tid >> 5;
    const int wm = warp >> 1 >> 1 ? 0 : 0;  // placeholder (computed below)
    (void)wm;
    const int wmm = (warp >> 2);            // 0..1
    const int wnn = (warp & 3);             // 0..3
    const int gid = lane >> 2, tig = lane & 3;
    const int nBase = nTile * 64;
    const int mBase = mTile * 64;

    const int lm = tid >> 2;                // loader row 0..63
    const int lq = (tid & 3) * 8;           // k offset within 32 (0,8,16,24)

    const int Ktot = X2 ? 1024 : 512;

    float acc[2][2][4];
#pragma unroll
    for (int i = 0; i < 2; i++)
#pragma unroll
        for (int j = 0; j < 2; j++)
#pragma unroll
            for (int c = 0; c < 4; c++) acc[i][j][c] = 0.f;

    // register prefetch: A = 8 floats of X, B = 8 halves of W
    float4 a0, a1; uint4 bW;
    a0 = *(const float4*)(X1 + (size_t)(mBase + lm) * 512 + lq);
    a1 = *(const float4*)(X1 + (size_t)(mBase + lm) * 512 + lq + 4);
    bW = *(const uint4*)(W1t + (size_t)(nBase + lm) * 512 + lq);

    for (int kt = 0; kt < Ktot; kt += 32) {
        __syncthreads();
        {
            __half2* ad = (__half2*)&sh->As[lm][lq];
            ad[0] = __floats2half2_rn(a0.x, a0.y);
            ad[1] = __floats2half2_rn(a0.z, a0.w);
            ad[2] = __floats2half2_rn(a1.x, a1.y);
            ad[3] = __floats2half2_rn(a1.z, a1.w);
            *(uint4*)&sh->Bs[lm][lq] = bW;
        }
        __syncthreads();

        const int kn = kt + 32;
        if (kn < Ktot) {
            const float*  X = (kn < 512) ? X1 : X2;
            const __half* W = (kn < 512) ? W1t : W2t;
            const int kk = kn & 511;
            a0 = *(const float4*)(X + (size_t)(mBase + lm) * 512 + kk + lq);
            a1 = *(const float4*)(X + (size_t)(mBase + lm) * 512 + kk + lq + 4);
            bW = *(const uint4*)(W + (size_t)(nBase + lm) * 512 + kk + lq);
        }

#pragma unroll
        for (int ks = 0; ks < 2; ks++) {
            unsigned af[2][4], bf2[2][2];
#pragma unroll
            for (int mf = 0; mf < 2; mf++) {
                const int m0 = wmm * 32 + mf * 16 + gid;
                const __half* ap  = &sh->As[m0][ks * 16];
                const __half* ap8 = &sh->As[m0 + 8][ks * 16];
                af[mf][0] = *(const unsigned*)(ap  + tig * 2);
                af[mf][1] = *(const unsigned*)(ap8 + tig * 2);
                af[mf][2] = *(const unsigned*)(ap  + 8 + tig * 2);
                af[mf][3] = *(const unsigned*)(ap8 + 8 + tig * 2);
            }
#pragma unroll
            for (int nf = 0; nf < 2; nf++) {
                const int n0 = wnn * 16 + nf * 8 + gid;
                const __half* bp = &sh->Bs[n0][ks * 16];
                bf2[nf][0] = *(const unsigned*)(bp + tig * 2);
                bf2[nf][1] = *(const unsigned*)(bp + 8 + tig * 2);
            }
#pragma unroll
            for (int mf = 0; mf < 2; mf++)
#pragma unroll
                for (int nf = 0; nf < 2; nf++)
                    mma_fp16(acc[mf][nf], af[mf], bf2[nf]);
        }
    }

    __syncthreads();
#pragma unroll
    for (int mf = 0; mf < 2; mf++) {
        const int row = wmm * 32 + mf * 16 + gid;
#pragma unroll
        for (int nf = 0; nf < 2; nf++) {
            const int col = wnn * 16 + nf * 8 + tig * 2;
            sh->Zs[row][col]         = acc[mf][nf][0];
            sh->Zs[row][col + 1]     = acc[mf][nf][1];
            sh->Zs[row + 8][col]     = acc[mf][nf][2];
            sh->Zs[row + 8][col + 1] = acc[mf][nf][3];
        }
    }
    __syncthreads();

    // Fused gating: 64 rows x 16 j per block; thread -> (row, 4 j's)
    const int r  = tid >> 2;
    const int j0 = (tid & 3) * 4;
    const int gr = mBase + r;
    int sym = 0;
    if (Ek0) sym = (tstep == 0) ? 111 : gt[gr * TSTEPS + tstep - 1];

#pragma unroll
    for (int jj = 0; jj < 4; jj++) {
        const int j  = j0 + jj;
        const int jg = nTile * 16 + j;
        float zi = sh->Zs[r][j * 4 + 0] + bias[jg];
        float zf = sh->Zs[r][j * 4 + 1] + bias[512 + jg];
        float zg = sh->Zs[r][j * 4 + 2] + bias[1024 + jg];
        float zo = sh->Zs[r][j * 4 + 3] + bias[1536 + jg];
        if (Ek0) {
            const float* e = Ek0 + (size_t)sym * 2048;
            zi += e[jg]; zf += e[512 + jg]; zg += e[1024 + jg]; zo += e[1536 + jg];
        }
        const float ci = c_in ? c_in[(size_t)gr * 512 + jg] : 0.f;
        const float si = 1.f / (1.f + expf(-zi));
        const float sf = 1.f / (1.f + expf(-zf));
        const float so = 1.f / (1.f + expf(-zo));
        const float c2 = sf * ci + si * tanhf(zg);
        const float h2 = so * tanhf(c2);
        h_out[(size_t)gr * 512 + jg] = h2;
        c_out[(size_t)gr * 512 + jg] = c2;
        if (h_out2) h_out2[(size_t)gr * 512 + jg] = h2;
    }
}

// ---------------------------------------------------------------------------
// Two-lane pipelined chain: 33 phases. Blocks 0..63 = cell0 lane (its own
// recurrence), blocks 64..127 = cell1 lane (consumes h0 one phase later).
//   phase 0:        cell0-prime
//   phase 1:        cell0(t=0)   || cell1-prime
//   phase p (2-31): cell0(t=p-1) || cell1(t=p-2)
//   phase 32:                       cell1(t=30)
// ---------------------------------------------------------------------------
__device__ void chain_body(
    ChainShH* sh, int cbid,
    const float* __restrict__ Ek0, const int* __restrict__ gt,
    const float* __restrict__ hol,
    const __half* __restrict__ k0t, const __half* __restrict__ rk0t,
    const __half* __restrict__ k1t, const __half* __restrict__ rk1t,
    const float* __restrict__ b0, const float* __restrict__ b1,
    float* __restrict__ st, float* __restrict__ h1all)
{
    const int clane = cbid >> 6;     // 0 = cell0 lane, 1 = cell1 lane
    const int u = cbid & 63;
    const int nTile = u & 31, mTile = u >> 5;
    float* h0b[2] = { st,          st + 65536 };
    float* c0b[2] = { st + 131072, st + 196608 };
    float* h1b[2] = { st + 262144, st + 327680 };
    float* c1b[2] = { st + 393216, st + 458752 };

    for (int p = 0; p <= 32; p++) {
        if (clane == 0) {
            if (p == 0) {
                // prime0: writes parity-1 buffers (acts as t = -1)
                lstm_cellh(sh, nTile, mTile, nullptr, nullptr, 0,
                           hol, k0t, nullptr, nullptr, b0, nullptr,
                           h0b[1], c0b[1], nullptr);
            } else if (p <= 31) {
                const int t = p - 1;
                lstm_cellh(sh, nTile, mTile, Ek0, gt, t,
                           h0b[(t + 1) & 1], rk0t, nullptr, nullptr, b0,
                           c0b[(t + 1) & 1], h0b[t & 1], c0b[t & 1], nullptr);
            }
        } else {
            if (p == 1) {
                // prime1: consumes h0 prime (phase 0 output)
                lstm_cellh(sh, nTile, mTile, nullptr, nullptr, 0,
                           h0b[1], k1t, nullptr, nullptr, b1, nullptr,
                           h1b[1], c1b[1], nullptr);
            } else if (p >= 2) {
                const int t = p - 2;
                lstm_cellh(sh, nTile, mTile, nullptr, nullptr, 0,
                           h0b[t & 1], k1t, h1b[(t + 1) & 1], rk1t, b1,
                           c1b[(t + 1) & 1], h1b[t & 1], c1b[t & 1],
                           h1all + (size_t)t * BB * 512);
            }
        }
        if (p < 32) grid_sync();
    }
}

// ---------------------------------------------------------------------------
// Fused kernel: bids 0..127 = pipelined LSTM chain (wave-1 resident -> grid
// barrier safe); bids 128..1151 = fp16 conv. Overlap on the chip.
// ---------------------------------------------------------------------------
__global__ __launch_bounds__(256, 2) void fused_conv_chain(
    const __half* __restrict__ Fh, const __half* __restrict__ Wth,
    const float* __restrict__ bf, float* __restrict__ fproj,
    const float* __restrict__ Ek0, const int* __restrict__ gt,
    const float* __restrict__ hol,
    const __half* __restrict__ k0t, const __half* __restrict__ rk0t,
    const __half* __restrict__ k1t, const __half* __restrict__ rk1t,
    const float* __restrict__ b0, const float* __restrict__ b1,
    float* __restrict__ st, float* __restrict__ h1all)
{
    extern __shared__ float smx[];
    if (blockIdx.x < (int)CHAIN_BLOCKS) {
        chain_body((ChainShH*)smx, blockIdx.x, Ek0, gt, hol,
                   k0t, rk0t, k1t, rk1t, b0, b1, st, h1all);
    } else {
        conv_body((__half*)smx, blockIdx.x - (int)CHAIN_BLOCKS, Fh, Wth, bf, fproj);
    }
}

// ---------------------------------------------------------------------------
// tf32 mma GEMM for hp = h1all @ Wh.  M=3968, N=512, K=512.
// ---------------------------------------------------------------------------
__device__ __forceinline__ float tf32r(float x) {
    unsigned u; asm("cvt.rna.tf32.f32 %0, %1;" : "=r"(u) : "f"(x));
    return __uint_as_float(u);
}
__global__ __launch_bounds__(256) void gemm_tc(
    const float* __restrict__ A, const float* __restrict__ W,
    float* __restrict__ C)
{
    __shared__ float As[2][128][20];
    __shared__ float Bs[2][16][132];

    const int tid = threadIdx.x;
    const int lane = tid & 31, warp = tid >> 5;
    const int wm = warp >> 2, wn = warp & 3;
    const int gid = lane >> 2, tig = lane & 3;
    const int mBase = blockIdx.y * 128, nBase = blockIdx.x * 128;

    const int am = tid >> 1;
    const int ak = (tid & 1) * 8;
    const int bk = tid >> 4;
    const int bn = (tid & 15) * 8;

    auto issue = [&](int kt, int s) {
        const float* p = A + (size_t)(mBase + am) * 512 + kt * 16 + ak;
        cp16(&As[s][am][ak],     p,     true);
        cp16(&As[s][am][ak + 4], p + 4, true);
        const float* q = W + (size_t)(kt * 16 + bk) * 512 + nBase + bn;
        cp16(&Bs[s][bk][bn],     q,     true);
        cp16(&Bs[s][bk][bn + 4], q + 4, true);
    };

    float acc[4][4][4];
#pragma unroll
    for (int i = 0; i < 4; i++)
#pragma unroll
        for (int j = 0; j < 4; j++)
#pragma unroll
            for (int c = 0; c < 4; c++) acc[i][j][c] = 0.f;

    issue(0, 0); CP_COMMIT();
    issue(1, 1); CP_COMMIT();

    const int NT = 32;
    for (int kt = 0; kt < NT; kt++) {
        const int s = kt & 1;
        if (kt + 1 < NT) { CP_WAIT(1); } else { CP_WAIT(0); }
        __syncthreads();
#pragma unroll
        for (int ks = 0; ks < 16; ks += 8) {
            unsigned afr[4][4], bfr[4][2];
#pragma unroll
            for (int mf = 0; mf < 4; mf++) {
                const int m0 = wm * 64 + mf * 16 + gid;
                afr[mf][0] = __float_as_uint(As[s][m0][ks + tig]);
                afr[mf][1] = __float_as_uint(As[s][m0 + 8][ks + tig]);
                afr[mf][2] = __float_as_uint(As[s][m0][ks + tig + 4]);
                afr[mf][3] = __float_as_uint(As[s][m0 + 8][ks + tig + 4]);
            }
#pragma unroll
            for (int nf = 0; nf < 4; nf++) {
                const int n0 = wn * 32 + nf * 8 + gid;
                bfr[nf][0] = __float_as_uint(Bs[s][ks + tig][n0]);
                bfr[nf][1] = __float_as_uint(Bs[s][ks + tig + 4][n0]);
            }
#pragma unroll
            for (int mf = 0; mf < 4; mf++)
#pragma unroll
                for (int nf = 0; nf < 4; nf++)
                    mma_tf32(acc[mf][nf], afr[mf], bfr[nf]);
        }
        __syncthreads();
        if (kt + 2 < NT) { issue(kt + 2, s); CP_COMMIT(); }
    }

#pragma unroll
    for (int mf = 0; mf < 4; mf++) {
        const int row = mBase + wm * 64 + mf * 16 + gid;
#pragma unroll
        for (int nf = 0; nf < 4; nf++) {
            const int col = nBase + wn * 32 + nf * 8 + tig * 2;
            C[(size_t)row * 512 + col]           = acc[mf][nf][0];
            C[(size_t)row * 512 + col + 1]       = acc[mf][nf][1];
            C[(size_t)(row + 8) * 512 + col]     = acc[mf][nf][2];
            C[(size_t)(row + 8) * 512 + col + 1] = acc[mf][nf][3];
        }
    }
}

// ---------------------------------------------------------------------------
// fp32 GEMM (logits): C = [A1|A2] @ W + bias, remapped out layout.
// ---------------------------------------------------------------------------
__global__ __launch_bounds__(256) void gemm_fused(
    const float* __restrict__ A1, const float* __restrict__ A2,
    const float* __restrict__ W, const float* __restrict__ bias,
    float* __restrict__ C, int N, int K)
{
    __shared__ float sA[16][65];
    __shared__ float sB[16][68];
    const int tid = threadIdx.x;
    const int tx = tid & 15, ty = tid >> 4;
    const int mBase = blockIdx.y * 64, nBase = blockIdx.x * 64;

    const int lam = tid >> 2, lak = (tid & 3) * 4;
    const int lbk = tid >> 4, lbn = (tid & 15) * 4;

    float acc[4][4];
#pragma unroll
    for (int i = 0; i < 4; i++)
#pragma unroll
        for (int j = 0; j < 4; j++) acc[i][j] = 0.f;

    for (int k0 = 0; k0 < K; k0 += 16) {
        float av[4], bv[4];
#pragma unroll
        for (int i = 0; i < 4; i++) {
            const int kk = k0 + lak + i;
            av[i] = (kk < 512) ? A1[(size_t)(mBase + lam) * 512 + kk]
                               : A2[(size_t)(mBase + lam) * 512 + kk - 512];
        }
#pragma unroll
        for (int i = 0; i < 4; i++) {
            const int nn = nBase + lbn + i;
            bv[i] = (nn < N) ? W[(size_t)(k0 + lbk) * N + nn] : 0.f;
        }
        __syncthreads();
#pragma unroll
        for (int i = 0; i < 4; i++) sA[lak + i][lam] = av[i];
#pragma unroll
        for (int i = 0; i < 4; i++) sB[lbk][lbn + i] = bv[i];
        __syncthreads();
#pragma unroll
        for (int kk = 0; kk < 16; kk++) {
            float a[4], b[4];
#pragma unroll
            for (int i = 0; i < 4; i++) a[i] = sA[kk][ty * 4 + i];
#pragma unroll
            for (int j = 0; j < 4; j++) b[j] = sB[kk][tx * 4 + j];
#pragma unroll
            for (int i = 0; i < 4; i++)
#pragma unroll
                for (int j = 0; j < 4; j++) acc[i][j] += a[i] * b[j];
        }
    }

#pragma unroll
    for (int i = 0; i < 4; i++) {
        const int row = mBase + ty * 4 + i;
#pragma unroll
        for (int j = 0; j < 4; j++) {
            const int col = nBase + tx * 4 + j;
            if (col < N) {
                const float v = acc[i][j] + bias[col];
                const int t = row >> 7, b = row & 127;
                C[(size_t)(b * TSTEPS + t) * NCLS + col] = v;
            }
        }
    }
}

// ---------------------------------------------------------------------------
// Attention logits: att[t,b,pos] = sum_ch tanh(fproj[b,pos,ch]+hp[t,b,ch])*wa[ch]
// fproj register-resident (read once). grid (8 pos-chunks, 128 b), 256 thr
// ---------------------------------------------------------------------------
__global__ __launch_bounds__(256) void att_kernel(
    const float* __restrict__ fproj, const float* __restrict__ hp,
    const float* __restrict__ wa, float* __restrict__ att)
{
    __shared__ float sHp[8 * 65];
    __shared__ float sWa[8 * 65];
    const int tid = threadIdx.x;
    const int posl = tid >> 3, tch = tid & 7;
    const int b = blockIdx.y, pos0 = blockIdx.x * 32;
    const int ch0 = tch * 64;

    float fr[64];
    const float* fp = fproj + (size_t)(b * NPOS + pos0 + posl) * 512 + ch0;
#pragma unroll
    for (int i = 0; i < 16; i++) {
        const float4 v = *(const float4*)(fp + i * 4);
        fr[i * 4 + 0] = v.x; fr[i * 4 + 1] = v.y;
        fr[i * 4 + 2] = v.z; fr[i * 4 + 3] = v.w;
    }
    for (int k = tid; k < 512; k += 256)
        sWa[(k >> 6) * 65 + (k & 63)] = wa[k];

    for (int t = 0; t < TSTEPS; t++) {
        __syncthreads();
        const float* hrow = hp + (size_t)(t * BB + b) * 512;
        for (int k = tid; k < 512; k += 256)
            sHp[(k >> 6) * 65 + (k & 63)] = hrow[k];
        __syncthreads();
        float s = 0.f;
#pragma unroll
        for (int i = 0; i < 64; i++) {
            const float x = fr[i] + sHp[tch * 65 + i];
            s += fast_tanh(x) * sWa[tch * 65 + i];
        }
        s += __shfl_down_sync(0xffffffffu, s, 4, 8);
        s += __shfl_down_sync(0xffffffffu, s, 2, 8);
        s += __shfl_down_sync(0xffffffffu, s, 1, 8);
        if (tch == 0)
            att[(size_t)(t * BB + b) * NPOS + pos0 + posl] = s;
    }
}

// ---------------------------------------------------------------------------
// Softmax over 256 positions per (t,b). grid 3968, 256 threads
// ---------------------------------------------------------------------------
__global__ __launch_bounds__(256) void softmax_kernel(float* __restrict__ att)
{
    const int row = blockIdx.x, tid = threadIdx.x;
    const int lane = tid & 31, warp = tid >> 5;
    __shared__ float rmax[8], rsum[8];
    const float v = att[(size_t)row * NPOS + tid];
    float m = v;
#pragma unroll
    for (int o = 16; o; o >>= 1) m = fmaxf(m, __shfl_xor_sync(0xffffffffu, m, o));
    if (lane == 0) rmax[warp] = m;
    __syncthreads();
    float M = rmax[0];
#pragma unroll
    for (int i = 1; i < 8; i++) M = fmaxf(M, rmax[i]);
    const float e = __expf(v - M);
    float s = e;
#pragma unroll
    for (int o = 16; o; o >>= 1) s += __shfl_xor_sync(0xffffffffu, s, o);
    if (lane == 0) rsum[warp] = s;
    __syncthreads();
    float S = 0.f;
#pragma unroll
    for (int i = 0; i < 8; i++) S += rsum[i];
    att[(size_t)row * NPOS + tid] = e / S;
}

// ---------------------------------------------------------------------------
// Glimpse: glim[t,b,c] = sum_pos att[t,b,pos] * features[b,pos,c]
// ---------------------------------------------------------------------------
__global__ __launch_bounds__(256) void glimpse_kernel(
    const float* __restrict__ F, const float* __restrict__ att,
    float* __restrict__ glim)
{
    __shared__ float sF[NPOS * 32];
    __shared__ float sA[NPOS];
    __shared__ float sP[8][33];
    const int tid = threadIdx.x;
    const int b = blockIdx.y, ch0 = blockIdx.x * 32;

    for (int idx = tid; idx < NPOS * 32; idx += 256) {
        const int pos = idx >> 5, ch = idx & 31;
        sF[pos * 32 + ch] = F[(size_t)(b * NPOS + pos) * 512 + ch0 + ch];
    }
    const int pg = tid >> 5, ch = tid & 31;

    for (int t = 0; t < TSTEPS; t++) {
        __syncthreads();
        sA[tid] = att[(size_t)(t * BB + b) * NPOS + tid];
        __syncthreads();
        float s = 0.f;
#pragma unroll
        for (int p = 0; p < 32; p++)
            s += sA[pg * 32 + p] * sF[(pg * 32 + p) * 32 + ch];
        sP[pg][ch] = s;
        __syncthreads();
        if (tid < 32) {
            float g = 0.f;
#pragma unroll
            for (int i = 0; i < 8; i++) g += sP[i][tid];
            glim[(size_t)(t * BB + b) * 512 + ch0 + tid] = g;
        }
    }
}

// ---------------------------------------------------------------------------
// Launch
// ---------------------------------------------------------------------------
extern "C" void kernel_launch(void* const* d_in, const int* in_sizes, int n_in,
                              void* d_out, int out_size)
{
    const float* features = (const float*)d_in[0];
    const float* holistic = (const float*)d_in[1];
    const int*   gt       = (const int*)  d_in[2];
    const float* embed_W  = (const float*)d_in[3];
    const float* k0   = (const float*)d_in[4];
    const float* rk0  = (const float*)d_in[5];
    const float* b0   = (const float*)d_in[6];
    const float* k1   = (const float*)d_in[7];
    const float* rk1  = (const float*)d_in[8];
    const float* b1   = (const float*)d_in[9];
    const float* Wh   = (const float*)d_in[10];
    const float* Wf   = (const float*)d_in[11];
    const float* bf   = (const float*)d_in[12];
    const float* wa   = (const float*)d_in[13];
    const float* outW = (const float*)d_in[14];
    const float* outb = (const float*)d_in[15];
    float* out = (float*)d_out;

    float* S = nullptr;
    cudaGetSymbolAddress((void**)&S, g_scratch);

    float* fproj = S + OF_FPROJ;
    float* Ek0   = S + OF_EK0;
    float* st    = S + OF_ST;
    float* h1all = S + OF_H1ALL;
    float* hp    = S + OF_HP;
    float* att   = S + OF_ATT;
    float* glim  = S + OF_GLIM;
    __half* k0t  = (__half*)(S + OF_WT);
    __half* rk0t = k0t + 1048576;
    __half* k1t  = k0t + 2097152;
    __half* rk1t = k0t + 3145728;
    __half* Fh   = (__half*)(S + OF_FH);
    __half* Wth  = (__half*)(S + OF_WTH);

    cudaFuncSetAttribute(fused_conv_chain,
        cudaFuncAttributeMaxDynamicSharedMemorySize, CONV_SMEM);

    // prep: fp16 conversions, fp16 gate-interleaved transposed LSTM weights
    prep_half<<<65536 + 2304, 256>>>(features, Wf, Fh, Wth);
    reorder_w4h<<<dim3(2048, 4), 256>>>(k0, rk0, k1, rk1, k0t);
    ek0_kernel<<<dim3(8, 112), 256>>>(embed_W, k0, Ek0);

    // fp16 conv + two-lane pipelined LSTM chain overlapped in ONE launch
    fused_conv_chain<<<128 + 1024, 256, CONV_SMEM>>>(
        Fh, Wth, bf, fproj,
        Ek0, gt, holistic, k0t, rk0t, k1t, rk1t, b0, b1, st, h1all);

    // batched epilogue over all 31 steps
    gemm_tc<<<dim3(4, 31), 256>>>(h1all, Wh, hp);
    att_kernel<<<dim3(8, 128), 256>>>(fproj, hp, wa, att);
    softmax_kernel<<<TSTEPS * BB, 256>>>(att);
    glimpse_kernel<<<dim3(16, 128), 256>>>(features, att, glim);
    gemm_fused<<<dim3(2, 62), 256>>>(h1all, glim, outW, outb, out, NCLS, 1024);
}